// round 3
// baseline (speedup 1.0000x reference)
#include <cuda_runtime.h>
#include <math.h>

// ---------------- problem constants ----------------
#define DMc   256
#define Lc    4096
#define DSc   128
#define DIc   512
#define NHc   8
#define HDc   64
#define CDc   768
#define DIPc  1288
#define CSc   256
#define NCc   16
#define EPSc  1e-5f

// ---------------- device scratch (static, allocation-free) ----------------
__device__ float g_U  [4 * Lc * DMc];                 // per-dir gathered input (l, m)
__device__ float g_Z  [4 * Lc * DIPc];                // in-proj output  (l, 1288)
__device__ float g_xBC[4 * Lc * CDc];                 // post conv+silu  (l, 768)  [x|B|C]
__device__ float g_dt [4 * Lc * NHc];                 // softplus dt
__device__ float g_dA [4 * Lc * NHc];                 // cumsum(dt*A) per chunk
__device__ float g_CB [4 * NCc * CSc * CSc];          // C B^T per (d,c)
__device__ float g_y  [4 * Lc * DIc];                 // y (diag, then +off+skip, then normed)
__device__ float g_st [4 * NCc * NHc * HDc * DSc];    // chunk states  (p,n)
__device__ float g_pv [4 * NCc * NHc * HDc * DSc];    // inter-chunk prev states
__device__ float g_cat[Lc * 4 * DMc];                 // concat buffer (l, 1024)

__device__ __forceinline__ float silu_f(float x) { return x / (1.f + __expf(-x)); }

// ---------------- 0. gather + transpose: U[d][l][m] = pts[m][perm_d(l)] ----------------
__global__ void k_buildU(const float* __restrict__ pts) {
    int d  = blockIdx.z;
    int lt = blockIdx.x * 32;   // l tile
    int mt = blockIdx.y * 32;   // m tile
    __shared__ float tile[32][33];
    int tx = threadIdx.x, ty = threadIdx.y;
    #pragma unroll
    for (int r = 0; r < 4; r++) {
        int i = ty + r * 8;                 // m-local
        int l = lt + tx;
        int lp;
        if      (d == 0) lp = l;
        else if (d == 1) lp = 4095 - l;
        else if (d == 2) lp = (l & 63) * 64 + (l >> 6);
        else             { int lv = 4095 - l; lp = (lv & 63) * 64 + (lv >> 6); }
        tile[i][tx] = pts[(mt + i) * Lc + lp];
    }
    __syncthreads();
    #pragma unroll
    for (int r = 0; r < 4; r++) {
        int i = ty + r * 8;                 // l-local
        g_U[(size_t)(d * Lc + lt + i) * DMc + mt + tx] = tile[tx][i];
    }
}

// ---------------- 1. in-proj GEMM-NT: Z = U(4096x256) @ Win(1288x256)^T ----------------
__global__ void __launch_bounds__(256) k_inproj(const float* __restrict__ Win) {
    int d = blockIdx.z;
    int m0 = blockIdx.x * 64, n0 = blockIdx.y * 64;
    const float* A = g_U + (size_t)d * Lc * DMc;
    const float* B = Win + (size_t)d * DIPc * DMc;
    __shared__ float As[16][65], Bs[16][65];
    int tid = threadIdx.x, tx = tid & 15, ty = tid >> 4;
    float acc[4][4] = {};
    for (int k0 = 0; k0 < 256; k0 += 16) {
        {
            int e = tid * 4, kk = e & 15, mm = e >> 4;
            float4 v = *(const float4*)(A + (m0 + mm) * 256 + k0 + kk);
            As[kk][mm] = v.x; As[kk+1][mm] = v.y; As[kk+2][mm] = v.z; As[kk+3][mm] = v.w;
        }
        {
            int e = tid * 4, kk = e & 15, nn = e >> 4;
            int n = n0 + nn;
            float4 v = make_float4(0.f,0.f,0.f,0.f);
            if (n < DIPc) v = *(const float4*)(B + n * 256 + k0 + kk);
            Bs[kk][nn] = v.x; Bs[kk+1][nn] = v.y; Bs[kk+2][nn] = v.z; Bs[kk+3][nn] = v.w;
        }
        __syncthreads();
        #pragma unroll
        for (int kk = 0; kk < 16; kk++) {
            float a[4], b[4];
            #pragma unroll
            for (int i = 0; i < 4; i++) a[i] = As[kk][ty*4+i];
            #pragma unroll
            for (int j = 0; j < 4; j++) b[j] = Bs[kk][tx*4+j];
            #pragma unroll
            for (int i = 0; i < 4; i++)
                #pragma unroll
                for (int j = 0; j < 4; j++) acc[i][j] += a[i] * b[j];
        }
        __syncthreads();
    }
    #pragma unroll
    for (int i = 0; i < 4; i++) {
        int m = m0 + ty*4 + i;
        #pragma unroll
        for (int j = 0; j < 4; j++) {
            int n = n0 + tx*4 + j;
            if (n < DIPc) g_Z[(size_t)(d * Lc + m) * DIPc + n] = acc[i][j];
        }
    }
}

// ---------------- 2. conv1d(width4, causal) + silu ; dt = softplus(dt+bias) ----------------
__global__ void __launch_bounds__(256) k_conv(const float* __restrict__ conv_w,
                                              const float* __restrict__ conv_b,
                                              const float* __restrict__ dt_bias) {
    int l = blockIdx.x, d = blockIdx.y, tid = threadIdx.x;
    for (int ch = tid; ch < CDc; ch += 256) {
        float acc = conv_b[d * CDc + ch];
        const float* cw = conv_w + (size_t)(d * CDc + ch) * 4;
        #pragma unroll
        for (int w = 0; w < 4; w++) {
            int ls = l - 3 + w;
            if (ls >= 0)
                acc += g_Z[(size_t)(d * Lc + ls) * DIPc + DIc + ch] * cw[w];
        }
        g_xBC[(size_t)(d * Lc + l) * CDc + ch] = silu_f(acc);
    }
    if (tid < NHc) {
        float v = g_Z[(size_t)(d * Lc + l) * DIPc + (DIc + CDc) + tid] + dt_bias[d * NHc + tid];
        float sp = (v > 20.f) ? v : log1pf(__expf(v));
        g_dt[(size_t)(d * Lc + l) * NHc + tid] = sp;
    }
}

// ---------------- 3. per-chunk inclusive cumsum of dt*A ----------------
__global__ void __launch_bounds__(256) k_scan(const float* __restrict__ A_log) {
    int c = blockIdx.x, h = blockIdx.y, d = blockIdx.z, s = threadIdx.x;
    float A = -__expf(A_log[d * NHc + h]);
    __shared__ float buf[256];
    buf[s] = g_dt[(size_t)(d * Lc + c * CSc + s) * NHc + h] * A;
    __syncthreads();
    for (int off = 1; off < 256; off <<= 1) {
        float t = (s >= off) ? buf[s - off] : 0.f;
        __syncthreads();
        buf[s] += t;
        __syncthreads();
    }
    g_dA[(size_t)(d * Lc + c * CSc + s) * NHc + h] = buf[s];
}

// ---------------- 4. CB[i][j] = C_i . B_j   (per d,c; K=128) ----------------
__global__ void __launch_bounds__(256) k_cb() {
    int dc = blockIdx.z; int d = dc >> 4, c = dc & 15;
    int i0 = blockIdx.x * 64, j0 = blockIdx.y * 64;
    __shared__ float As[16][65], Bs[16][65];
    int tid = threadIdx.x, tx = tid & 15, ty = tid >> 4;
    const float* base = g_xBC + (size_t)(d * Lc + c * CSc) * CDc;
    float acc[4][4] = {};
    for (int k0 = 0; k0 < 128; k0 += 16) {
        int e = tid * 4, kk = e & 15, rr = e >> 4;
        {
            float4 v = *(const float4*)(base + (i0 + rr) * CDc + (DIc + DSc) + k0 + kk);
            As[kk][rr] = v.x; As[kk+1][rr] = v.y; As[kk+2][rr] = v.z; As[kk+3][rr] = v.w;
        }
        {
            float4 v = *(const float4*)(base + (j0 + rr) * CDc + DIc + k0 + kk);
            Bs[kk][rr] = v.x; Bs[kk+1][rr] = v.y; Bs[kk+2][rr] = v.z; Bs[kk+3][rr] = v.w;
        }
        __syncthreads();
        #pragma unroll
        for (int kk2 = 0; kk2 < 16; kk2++) {
            float a[4], b[4];
            #pragma unroll
            for (int i = 0; i < 4; i++) a[i] = As[kk2][ty*4+i];
            #pragma unroll
            for (int j = 0; j < 4; j++) b[j] = Bs[kk2][tx*4+j];
            #pragma unroll
            for (int i = 0; i < 4; i++)
                #pragma unroll
                for (int j = 0; j < 4; j++) acc[i][j] += a[i] * b[j];
        }
        __syncthreads();
    }
    float* out = g_CB + (size_t)(d * NCc + c) * CSc * CSc;
    #pragma unroll
    for (int i = 0; i < 4; i++)
        #pragma unroll
        for (int j = 0; j < 4; j++)
            out[(i0 + ty*4 + i) * CSc + j0 + tx*4 + j] = acc[i][j];
}

// ---------------- 5. y_diag = (CB . mask . exp(dAi-dAj) . dt_j) @ X ----------------
__global__ void __launch_bounds__(256) k_ydiag() {
    int bi = blockIdx.x;
    int z  = blockIdx.z; int d = z >> 7, c = (z >> 3) & 15, h = z & 7;
    __shared__ float Ss[16][65], Xs[16][65];
    __shared__ float daF[256], dtF[256];
    int tid = threadIdx.x, tx = tid & 15, ty = tid >> 4;
    int i0 = bi * 64;
    daF[tid] = g_dA[(size_t)(d * Lc + c * CSc + tid) * NHc + h];
    dtF[tid] = g_dt[(size_t)(d * Lc + c * CSc + tid) * NHc + h];
    __syncthreads();
    const float* cbb = g_CB + (size_t)(d * NCc + c) * CSc * CSc;
    const float* xbase = g_xBC + (size_t)(d * Lc + c * CSc) * CDc + h * HDc;
    float acc[4][4] = {};
    for (int j0 = 0; j0 < 256; j0 += 16) {
        {   // score tile: Ss[j][i]
            int e = tid * 4, kk = e & 15, ii = e >> 4;
            float4 v = *(const float4*)(cbb + (i0 + ii) * CSc + j0 + kk);
            float r[4] = {v.x, v.y, v.z, v.w};
            float dai = daF[i0 + ii];
            int ig = i0 + ii;
            #pragma unroll
            for (int q = 0; q < 4; q++) {
                int jg = j0 + kk + q;
                float sv = 0.f;
                if (jg <= ig) sv = r[q] * __expf(dai - daF[jg]) * dtF[jg];
                Ss[kk + q][ii] = sv;
            }
        }
        {   // X tile: Xs[j][p]
            int e = tid * 4, p = e & 63, jj = e >> 6;
            float4 v = *(const float4*)(xbase + (j0 + jj) * CDc + p);
            Xs[jj][p] = v.x; Xs[jj][p+1] = v.y; Xs[jj][p+2] = v.z; Xs[jj][p+3] = v.w;
        }
        __syncthreads();
        #pragma unroll
        for (int kk = 0; kk < 16; kk++) {
            float a[4], b[4];
            #pragma unroll
            for (int i = 0; i < 4; i++) a[i] = Ss[kk][ty*4+i];
            #pragma unroll
            for (int j = 0; j < 4; j++) b[j] = Xs[kk][tx*4+j];
            #pragma unroll
            for (int i = 0; i < 4; i++)
                #pragma unroll
                for (int j = 0; j < 4; j++) acc[i][j] += a[i] * b[j];
        }
        __syncthreads();
    }
    #pragma unroll
    for (int i = 0; i < 4; i++)
        #pragma unroll
        for (int j = 0; j < 4; j++)
            g_y[(size_t)(d * Lc + c * CSc + i0 + ty*4 + i) * DIc + h * HDc + tx*4 + j] = acc[i][j];
}

// ---------------- 6. states[p][n] = sum_s X[s][p] * w[s] * B[s][n] ----------------
__global__ void __launch_bounds__(256) k_states() {
    int bn = blockIdx.x;                 // n tile (0..1)
    int z  = blockIdx.z; int d = z >> 7, c = (z >> 3) & 15, h = z & 7;
    __shared__ float Aw[16][65], Bsh[16][65];
    __shared__ float daF[256], dtF[256];
    int tid = threadIdx.x, tx = tid & 15, ty = tid >> 4;
    daF[tid] = g_dA[(size_t)(d * Lc + c * CSc + tid) * NHc + h];
    dtF[tid] = g_dt[(size_t)(d * Lc + c * CSc + tid) * NHc + h];
    __syncthreads();
    float daL = daF[255];
    const float* base = g_xBC + (size_t)(d * Lc + c * CSc) * CDc;
    int n0 = bn * 64;
    float acc[4][4] = {};
    for (int s0 = 0; s0 < 256; s0 += 16) {
        int e = tid * 4, col = e & 63, ss = e >> 6;
        float w = dtF[s0 + ss] * __expf(daL - daF[s0 + ss]);
        {
            float4 v = *(const float4*)(base + (s0 + ss) * CDc + h * HDc + col);
            Aw[ss][col] = v.x * w; Aw[ss][col+1] = v.y * w; Aw[ss][col+2] = v.z * w; Aw[ss][col+3] = v.w * w;
        }
        {
            float4 v = *(const float4*)(base + (s0 + ss) * CDc + DIc + n0 + col);
            Bsh[ss][col] = v.x; Bsh[ss][col+1] = v.y; Bsh[ss][col+2] = v.z; Bsh[ss][col+3] = v.w;
        }
        __syncthreads();
        #pragma unroll
        for (int kk = 0; kk < 16; kk++) {
            float a[4], b[4];
            #pragma unroll
            for (int i = 0; i < 4; i++) a[i] = Aw[kk][ty*4+i];
            #pragma unroll
            for (int j = 0; j < 4; j++) b[j] = Bsh[kk][tx*4+j];
            #pragma unroll
            for (int i = 0; i < 4; i++)
                #pragma unroll
                for (int j = 0; j < 4; j++) acc[i][j] += a[i] * b[j];
        }
        __syncthreads();
    }
    float* out = g_st + (size_t)((d * NCc + c) * NHc + h) * HDc * DSc;
    #pragma unroll
    for (int i = 0; i < 4; i++)
        #pragma unroll
        for (int j = 0; j < 4; j++)
            out[(ty*4 + i) * DSc + n0 + tx*4 + j] = acc[i][j];
}

// ---------------- 7. sequential inter-chunk scan (tiny) ----------------
__global__ void __launch_bounds__(256) k_chunkscan() {
    int dh = blockIdx.x; int d = dh >> 3, h = dh & 7;
    int tid = threadIdx.x;
    float carry[32];
    #pragma unroll
    for (int t = 0; t < 32; t++) carry[t] = 0.f;
    for (int c = 0; c < NCc; c++) {
        float cd = __expf(g_dA[(size_t)(d * Lc + c * CSc + 255) * NHc + h]);
        size_t off = (size_t)((d * NCc + c) * NHc + h) * 8192;
        #pragma unroll
        for (int t = 0; t < 32; t++) {
            int e = tid + t * 256;
            g_pv[off + e] = carry[t];
            carry[t] = carry[t] * cd + g_st[off + e];
        }
    }
}

// ---------------- 8. y += exp(dA_i) * (C @ prev^T) + D*x ----------------
__global__ void __launch_bounds__(256) k_yoff(const float* __restrict__ D_param) {
    int bi = blockIdx.x;
    int z  = blockIdx.z; int d = z >> 7, c = (z >> 3) & 15, h = z & 7;
    __shared__ float Cs[16][65], Ps[16][65];
    __shared__ float daI[64];
    int tid = threadIdx.x, tx = tid & 15, ty = tid >> 4;
    int i0 = bi * 64;
    if (tid < 64) daI[tid] = g_dA[(size_t)(d * Lc + c * CSc + i0 + tid) * NHc + h];
    const float* base = g_xBC + (size_t)(d * Lc + c * CSc) * CDc;
    const float* pv = g_pv + (size_t)((d * NCc + c) * NHc + h) * HDc * DSc;
    float acc[4][4] = {};
    for (int k0 = 0; k0 < 128; k0 += 16) {
        int e = tid * 4, kk = e & 15, rr = e >> 4;
        {
            float4 v = *(const float4*)(base + (i0 + rr) * CDc + (DIc + DSc) + k0 + kk);
            Cs[kk][rr] = v.x; Cs[kk+1][rr] = v.y; Cs[kk+2][rr] = v.z; Cs[kk+3][rr] = v.w;
        }
        {
            float4 v = *(const float4*)(pv + rr * DSc + k0 + kk);
            Ps[kk][rr] = v.x; Ps[kk+1][rr] = v.y; Ps[kk+2][rr] = v.z; Ps[kk+3][rr] = v.w;
        }
        __syncthreads();
        #pragma unroll
        for (int kk2 = 0; kk2 < 16; kk2++) {
            float a[4], b[4];
            #pragma unroll
            for (int i = 0; i < 4; i++) a[i] = Cs[kk2][ty*4+i];
            #pragma unroll
            for (int j = 0; j < 4; j++) b[j] = Ps[kk2][tx*4+j];
            #pragma unroll
            for (int i = 0; i < 4; i++)
                #pragma unroll
                for (int j = 0; j < 4; j++) acc[i][j] += a[i] * b[j];
        }
        __syncthreads();
    }
    float Dh = D_param[d * NHc + h];
    #pragma unroll
    for (int i = 0; i < 4; i++) {
        float ei = __expf(daI[ty*4 + i]);
        int lg = c * CSc + i0 + ty*4 + i;
        #pragma unroll
        for (int j = 0; j < 4; j++) {
            int p = tx*4 + j;
            size_t yi = (size_t)(d * Lc + lg) * DIc + h * HDc + p;
            float xv = g_xBC[(size_t)(d * Lc + lg) * CDc + h * HDc + p];
            g_y[yi] = g_y[yi] + ei * acc[i][j] + Dh * xv;
        }
    }
}

// ---------------- 9. gate with silu(z), RMSNorm * norm_w ----------------
__global__ void __launch_bounds__(256) k_norm(const float* __restrict__ norm_w) {
    int l = blockIdx.x, d = blockIdx.y, tid = threadIdx.x;
    float v[2]; float ss = 0.f;
    #pragma unroll
    for (int t = 0; t < 2; t++) {
        int j = tid + t * 256;
        float zz = g_Z[(size_t)(d * Lc + l) * DIPc + j];
        float yy = g_y[(size_t)(d * Lc + l) * DIc + j];
        float val = yy * silu_f(zz);
        v[t] = val; ss += val * val;
    }
    __shared__ float red[256];
    red[tid] = ss; __syncthreads();
    for (int o = 128; o > 0; o >>= 1) { if (tid < o) red[tid] += red[tid + o]; __syncthreads(); }
    float scale = rsqrtf(red[0] / (float)DIc + EPSc);
    #pragma unroll
    for (int t = 0; t < 2; t++) {
        int j = tid + t * 256;
        g_y[(size_t)(d * Lc + l) * DIc + j] = v[t] * scale * norm_w[d * DIc + j];
    }
}

// ---------------- 10. out-proj GEMM + permuted scatter into concat ----------------
__global__ void __launch_bounds__(256) k_outproj(const float* __restrict__ Wout) {
    int d = blockIdx.z;
    int m0 = blockIdx.x * 64, n0 = blockIdx.y * 64;
    const float* A = g_y + (size_t)d * Lc * DIc;
    const float* B = Wout + (size_t)d * DMc * DIc;
    __shared__ float As[16][65], Bs[16][65];
    int tid = threadIdx.x, tx = tid & 15, ty = tid >> 4;
    float acc[4][4] = {};
    for (int k0 = 0; k0 < 512; k0 += 16) {
        int e = tid * 4, kk = e & 15, rr = e >> 4;
        {
            float4 v = *(const float4*)(A + (m0 + rr) * DIc + k0 + kk);
            As[kk][rr] = v.x; As[kk+1][rr] = v.y; As[kk+2][rr] = v.z; As[kk+3][rr] = v.w;
        }
        {
            float4 v = *(const float4*)(B + (n0 + rr) * DIc + k0 + kk);
            Bs[kk][rr] = v.x; Bs[kk+1][rr] = v.y; Bs[kk+2][rr] = v.z; Bs[kk+3][rr] = v.w;
        }
        __syncthreads();
        #pragma unroll
        for (int kk2 = 0; kk2 < 16; kk2++) {
            float a[4], b[4];
            #pragma unroll
            for (int i = 0; i < 4; i++) a[i] = As[kk2][ty*4+i];
            #pragma unroll
            for (int j = 0; j < 4; j++) b[j] = Bs[kk2][tx*4+j];
            #pragma unroll
            for (int i = 0; i < 4; i++)
                #pragma unroll
                for (int j = 0; j < 4; j++) acc[i][j] += a[i] * b[j];
        }
        __syncthreads();
    }
    #pragma unroll
    for (int i = 0; i < 4; i++) {
        int l = m0 + ty*4 + i;
        int r;
        if      (d == 0) r = l;
        else if (d == 1) r = 4095 - l;
        else if (d == 2) r = (l & 63) * 64 + (l >> 6);
        else             { int lv = 4095 - l; r = (lv & 63) * 64 + (lv >> 6); }
        #pragma unroll
        for (int j = 0; j < 4; j++)
            g_cat[(size_t)r * (4 * DMc) + d * DMc + n0 + tx*4 + j] = acc[i][j];
    }
}

// ---------------- 11. final GEMM with fused SiLU on A ----------------
__global__ void __launch_bounds__(256) k_final(const float* __restrict__ Wf,
                                               float* __restrict__ out) {
    int m0 = blockIdx.x * 64, n0 = blockIdx.y * 64;
    __shared__ float As[16][65], Bs[16][65];
    int tid = threadIdx.x, tx = tid & 15, ty = tid >> 4;
    float acc[4][4] = {};
    for (int k0 = 0; k0 < 1024; k0 += 16) {
        int e = tid * 4, kk = e & 15, rr = e >> 4;
        {
            float4 v = *(const float4*)(g_cat + (size_t)(m0 + rr) * 1024 + k0 + kk);
            As[kk][rr]   = silu_f(v.x);
            As[kk+1][rr] = silu_f(v.y);
            As[kk+2][rr] = silu_f(v.z);
            As[kk+3][rr] = silu_f(v.w);
        }
        {
            float4 v = *(const float4*)(Wf + (size_t)(n0 + rr) * 1024 + k0 + kk);
            Bs[kk][rr] = v.x; Bs[kk+1][rr] = v.y; Bs[kk+2][rr] = v.z; Bs[kk+3][rr] = v.w;
        }
        __syncthreads();
        #pragma unroll
        for (int kk2 = 0; kk2 < 16; kk2++) {
            float a[4], b[4];
            #pragma unroll
            for (int i = 0; i < 4; i++) a[i] = As[kk2][ty*4+i];
            #pragma unroll
            for (int j = 0; j < 4; j++) b[j] = Bs[kk2][tx*4+j];
            #pragma unroll
            for (int i = 0; i < 4; i++)
                #pragma unroll
                for (int j = 0; j < 4; j++) acc[i][j] += a[i] * b[j];
        }
        __syncthreads();
    }
    #pragma unroll
    for (int i = 0; i < 4; i++)
        #pragma unroll
        for (int j = 0; j < 4; j++)
            out[(size_t)(m0 + ty*4 + i) * DMc + n0 + tx*4 + j] = acc[i][j];
}

// ---------------- launcher ----------------
extern "C" void kernel_launch(void* const* d_in, const int* in_sizes, int n_in,
                              void* d_out, int out_size) {
    const float* pts      = (const float*)d_in[0];
    const float* in_proj  = (const float*)d_in[2];
    const float* conv_w   = (const float*)d_in[3];
    const float* conv_b   = (const float*)d_in[4];
    const float* dt_bias  = (const float*)d_in[5];
    const float* A_log    = (const float*)d_in[6];
    const float* D_param  = (const float*)d_in[7];
    const float* norm_w   = (const float*)d_in[8];
    const float* outp_w   = (const float*)d_in[9];
    const float* final_w  = (const float*)d_in[10];
    float* out = (float*)d_out;

    k_buildU  <<<dim3(128, 8, 4), dim3(32, 8)>>>(pts);
    k_inproj  <<<dim3(64, 21, 4), 256>>>(in_proj);
    k_conv    <<<dim3(4096, 4),   256>>>(conv_w, conv_b, dt_bias);
    k_scan    <<<dim3(16, 8, 4),  256>>>(A_log);
    k_cb      <<<dim3(4, 4, 64),  256>>>();
    k_ydiag   <<<dim3(4, 1, 512), 256>>>();
    k_states  <<<dim3(2, 1, 512), 256>>>();
    k_chunkscan<<<32, 256>>>();
    k_yoff    <<<dim3(4, 1, 512), 256>>>(D_param);
    k_norm    <<<dim3(4096, 4),   256>>>(norm_w);
    k_outproj <<<dim3(64, 4, 4),  256>>>(outp_w);
    k_final   <<<dim3(64, 4),     256>>>(final_w, out);
}

// round 5
// speedup vs baseline: 1.0635x; 1.0635x over previous
#include <cuda_runtime.h>
#include <math.h>

// ---------------- problem constants ----------------
#define DMc   256
#define Lc    4096
#define DSc   128
#define DIc   512
#define NHc   8
#define HDc   64
#define CDc   768
#define DIPc  1288
#define CSc   256
#define NCc   16
#define EPSc  1e-5f

// ---------------- device scratch ----------------
__device__ float g_U  [4 * Lc * DMc];
__device__ float g_Z  [4 * Lc * DIPc];
__device__ float g_xBC[4 * Lc * CDc];
__device__ float g_dt [4 * Lc * NHc];
__device__ float g_dA [4 * Lc * NHc];
__device__ float g_CB [4 * NCc * CSc * CSc];
__device__ float g_y  [4 * Lc * DIc];
__device__ float g_st [4 * NCc * NHc * HDc * DSc];
__device__ float g_pv [4 * NCc * NHc * HDc * DSc];
__device__ float g_cat[Lc * 4 * DMc];

__device__ __forceinline__ float silu_f(float x) { return x / (1.f + __expf(-x)); }

// ======== tile loaders: BK=16, 128-row tile (pad 132) and 64-row tile (pad 68) ========
__device__ __forceinline__ void ld128(const float* __restrict__ G, int ld, int k0,
                                      float (*S)[132], int tid) {
    #pragma unroll
    for (int h = 0; h < 2; h++) {
        int e = tid * 4 + h * 1024; int kk = e & 15; int rr = e >> 4;
        float4 v = *(const float4*)(G + (size_t)rr * ld + k0 + kk);
        S[kk][rr] = v.x; S[kk+1][rr] = v.y; S[kk+2][rr] = v.z; S[kk+3][rr] = v.w;
    }
}
__device__ __forceinline__ void ld128m(const float* __restrict__ G, int ld, int k0, int rlim,
                                       float (*S)[132], int tid) {
    #pragma unroll
    for (int h = 0; h < 2; h++) {
        int e = tid * 4 + h * 1024; int kk = e & 15; int rr = e >> 4;
        float4 v = make_float4(0.f, 0.f, 0.f, 0.f);
        if (rr < rlim) v = *(const float4*)(G + (size_t)rr * ld + k0 + kk);
        S[kk][rr] = v.x; S[kk+1][rr] = v.y; S[kk+2][rr] = v.z; S[kk+3][rr] = v.w;
    }
}
__device__ __forceinline__ void ld128s(const float* __restrict__ G, int ld, int k0,
                                       float (*S)[132], int tid) {   // silu applied
    #pragma unroll
    for (int h = 0; h < 2; h++) {
        int e = tid * 4 + h * 1024; int kk = e & 15; int rr = e >> 4;
        float4 v = *(const float4*)(G + (size_t)rr * ld + k0 + kk);
        S[kk][rr] = silu_f(v.x); S[kk+1][rr] = silu_f(v.y);
        S[kk+2][rr] = silu_f(v.z); S[kk+3][rr] = silu_f(v.w);
    }
}
__device__ __forceinline__ void ld64(const float* __restrict__ G, int ld, int k0,
                                     float (*S)[68], int tid) {
    int e = tid * 4; int kk = e & 15; int rr = e >> 4;    // rr 0..63
    float4 v = *(const float4*)(G + (size_t)rr * ld + k0 + kk);
    S[kk][rr] = v.x; S[kk+1][rr] = v.y; S[kk+2][rr] = v.z; S[kk+3][rr] = v.w;
}

// ======== microtile compute ========
__device__ __forceinline__ void fma8x8(const float (*As)[132], const float (*Bs)[132],
                                       float acc[8][8], int tx, int ty) {
    #pragma unroll
    for (int kk = 0; kk < 16; kk++) {
        float a[8], b[8];
        *(float4*)(a)     = *(const float4*)(&As[kk][ty*8]);
        *(float4*)(a + 4) = *(const float4*)(&As[kk][ty*8 + 4]);
        *(float4*)(b)     = *(const float4*)(&Bs[kk][tx*8]);
        *(float4*)(b + 4) = *(const float4*)(&Bs[kk][tx*8 + 4]);
        #pragma unroll
        for (int i = 0; i < 8; i++)
            #pragma unroll
            for (int j = 0; j < 8; j++) acc[i][j] += a[i] * b[j];
    }
}
__device__ __forceinline__ void fma8x4(const float (*As)[132], const float (*Bs)[68],
                                       float acc[8][4], int tx, int ty) {
    #pragma unroll
    for (int kk = 0; kk < 16; kk++) {
        float a[8], b[4];
        *(float4*)(a)     = *(const float4*)(&As[kk][ty*8]);
        *(float4*)(a + 4) = *(const float4*)(&As[kk][ty*8 + 4]);
        *(float4*)(b)     = *(const float4*)(&Bs[kk][tx*4]);
        #pragma unroll
        for (int i = 0; i < 8; i++)
            #pragma unroll
            for (int j = 0; j < 4; j++) acc[i][j] += a[i] * b[j];
    }
}
__device__ __forceinline__ void fma4x8(const float (*As)[68], const float (*Bs)[132],
                                       float acc[4][8], int tx, int ty) {
    #pragma unroll
    for (int kk = 0; kk < 16; kk++) {
        float a[4], b[8];
        *(float4*)(a)     = *(const float4*)(&As[kk][ty*4]);
        *(float4*)(b)     = *(const float4*)(&Bs[kk][tx*8]);
        *(float4*)(b + 4) = *(const float4*)(&Bs[kk][tx*8 + 4]);
        #pragma unroll
        for (int i = 0; i < 4; i++)
            #pragma unroll
            for (int j = 0; j < 8; j++) acc[i][j] += a[i] * b[j];
    }
}

// ---------------- 0. gather + transpose ----------------
__global__ void k_buildU(const float* __restrict__ pts) {
    int d  = blockIdx.z;
    int lt = blockIdx.x * 32;
    int mt = blockIdx.y * 32;
    __shared__ float tile[32][33];
    int tx = threadIdx.x, ty = threadIdx.y;
    #pragma unroll
    for (int r = 0; r < 4; r++) {
        int i = ty + r * 8;
        int l = lt + tx;
        int lp;
        if      (d == 0) lp = l;
        else if (d == 1) lp = 4095 - l;
        else if (d == 2) lp = (l & 63) * 64 + (l >> 6);
        else             { int lv = 4095 - l; lp = (lv & 63) * 64 + (lv >> 6); }
        tile[i][tx] = pts[(mt + i) * Lc + lp];
    }
    __syncthreads();
    #pragma unroll
    for (int r = 0; r < 4; r++) {
        int i = ty + r * 8;
        g_U[(size_t)(d * Lc + lt + i) * DMc + mt + tx] = tile[tx][i];
    }
}

// ---------------- 1. in-proj: Z = U(4096x256) @ Win(1288x256)^T ----------------
__global__ void __launch_bounds__(256) k_inproj(const float* __restrict__ Win) {
    int d = blockIdx.z;
    int m0 = blockIdx.x * 128, n0 = blockIdx.y * 128;
    const float* A = g_U + (size_t)d * Lc * DMc + (size_t)m0 * DMc;
    const float* B = Win + (size_t)d * DIPc * DMc + (size_t)n0 * DMc;
    int nrem = DIPc - n0;
    __shared__ float As[16][132], Bs[16][132];
    int tid = threadIdx.x, tx = tid & 15, ty = tid >> 4;
    float acc[8][8] = {};
    for (int k0 = 0; k0 < DMc; k0 += 16) {
        ld128 (A, DMc, k0, As, tid);
        ld128m(B, DMc, k0, nrem, Bs, tid);
        __syncthreads();
        fma8x8(As, Bs, acc, tx, ty);
        __syncthreads();
    }
    #pragma unroll
    for (int i = 0; i < 8; i++) {
        int m = m0 + ty*8 + i;
        #pragma unroll
        for (int j = 0; j < 8; j++) {
            int n = n0 + tx*8 + j;
            if (n < DIPc) g_Z[(size_t)(d * Lc + m) * DIPc + n] = acc[i][j];
        }
    }
}

// ---------------- 2. conv1d + silu ; softplus dt ----------------
__global__ void __launch_bounds__(256) k_conv(const float* __restrict__ conv_w,
                                              const float* __restrict__ conv_b,
                                              const float* __restrict__ dt_bias) {
    int l = blockIdx.x, d = blockIdx.y, tid = threadIdx.x;
    for (int ch = tid; ch < CDc; ch += 256) {
        float acc = conv_b[d * CDc + ch];
        const float* cw = conv_w + (size_t)(d * CDc + ch) * 4;
        #pragma unroll
        for (int w = 0; w < 4; w++) {
            int ls = l - 3 + w;
            if (ls >= 0)
                acc += g_Z[(size_t)(d * Lc + ls) * DIPc + DIc + ch] * cw[w];
        }
        g_xBC[(size_t)(d * Lc + l) * CDc + ch] = silu_f(acc);
    }
    if (tid < NHc) {
        float v = g_Z[(size_t)(d * Lc + l) * DIPc + (DIc + CDc) + tid] + dt_bias[d * NHc + tid];
        float sp = (v > 20.f) ? v : log1pf(__expf(v));
        g_dt[(size_t)(d * Lc + l) * NHc + tid] = sp;
    }
}

// ---------------- 3. per-chunk cumsum of dt*A ----------------
__global__ void __launch_bounds__(256) k_scan(const float* __restrict__ A_log) {
    int c = blockIdx.x, h = blockIdx.y, d = blockIdx.z, s = threadIdx.x;
    float A = -__expf(A_log[d * NHc + h]);
    __shared__ float buf[256];
    buf[s] = g_dt[(size_t)(d * Lc + c * CSc + s) * NHc + h] * A;
    __syncthreads();
    for (int off = 1; off < 256; off <<= 1) {
        float t = (s >= off) ? buf[s - off] : 0.f;
        __syncthreads();
        buf[s] += t;
        __syncthreads();
    }
    g_dA[(size_t)(d * Lc + c * CSc + s) * NHc + h] = buf[s];
}

// ---------------- 4. CB = C @ B^T  (256x256, K=128) ----------------
__global__ void __launch_bounds__(256) k_cb() {
    int dc = blockIdx.z; int d = dc >> 4, c = dc & 15;
    int i0 = blockIdx.x * 128, j0 = blockIdx.y * 128;
    const float* base = g_xBC + (size_t)(d * Lc + c * CSc) * CDc;
    const float* A = base + (size_t)i0 * CDc + (DIc + DSc);
    const float* B = base + (size_t)j0 * CDc + DIc;
    __shared__ float As[16][132], Bs[16][132];
    int tid = threadIdx.x, tx = tid & 15, ty = tid >> 4;
    float acc[8][8] = {};
    for (int k0 = 0; k0 < DSc; k0 += 16) {
        ld128(A, CDc, k0, As, tid);
        ld128(B, CDc, k0, Bs, tid);
        __syncthreads();
        fma8x8(As, Bs, acc, tx, ty);
        __syncthreads();
    }
    float* out = g_CB + (size_t)(d * NCc + c) * CSc * CSc;
    #pragma unroll
    for (int i = 0; i < 8; i++)
        #pragma unroll
        for (int j = 0; j < 8; j++)
            out[(i0 + ty*8 + i) * CSc + j0 + tx*8 + j] = acc[i][j];
}

// ---------------- 5. y_diag = (CB.mask.exp(dAi-dAj).dt_j) @ X ----------------
__global__ void __launch_bounds__(256) k_ydiag() {
    int i0 = blockIdx.x * 128;
    int z  = blockIdx.z; int d = z >> 7, c = (z >> 3) & 15, h = z & 7;
    __shared__ float Ss[16][132], Xs[16][68];
    __shared__ float daF[256], dtF[256];
    int tid = threadIdx.x, tx = tid & 15, ty = tid >> 4;
    daF[tid] = g_dA[(size_t)(d * Lc + c * CSc + tid) * NHc + h];
    dtF[tid] = g_dt[(size_t)(d * Lc + c * CSc + tid) * NHc + h];
    __syncthreads();
    const float* cbb   = g_CB + (size_t)(d * NCc + c) * CSc * CSc;
    const float* xbase = g_xBC + (size_t)(d * Lc + c * CSc) * CDc + h * HDc;
    float acc[8][4] = {};
    for (int j0 = 0; j0 < CSc; j0 += 16) {
        #pragma unroll
        for (int hh = 0; hh < 2; hh++) {    // score tile Ss[j][i]
            int e = tid * 4 + hh * 1024; int kk = e & 15; int ii = e >> 4;
            float4 v = *(const float4*)(cbb + (i0 + ii) * CSc + j0 + kk);
            float r[4] = {v.x, v.y, v.z, v.w};
            float dai = daF[i0 + ii];
            int ig = i0 + ii;
            #pragma unroll
            for (int q = 0; q < 4; q++) {
                int jg = j0 + kk + q;
                float sv = 0.f;
                if (jg <= ig) sv = r[q] * __expf(dai - daF[jg]) * dtF[jg];
                Ss[kk + q][ii] = sv;
            }
        }
        {   // X tile Xs[j][p]
            int e = tid * 4; int p = e & 63; int jj = e >> 6;
            float4 v = *(const float4*)(xbase + (size_t)(j0 + jj) * CDc + p);
            Xs[jj][p] = v.x; Xs[jj][p+1] = v.y; Xs[jj][p+2] = v.z; Xs[jj][p+3] = v.w;
        }
        __syncthreads();
        fma8x4(Ss, Xs, acc, tx, ty);
        __syncthreads();
    }
    #pragma unroll
    for (int i = 0; i < 8; i++)
        #pragma unroll
        for (int j = 0; j < 4; j++)
            g_y[(size_t)(d * Lc + c * CSc + i0 + ty*8 + i) * DIc + h * HDc + tx*4 + j] = acc[i][j];
}

// ---------------- 6. states[p][n] = sum_s X[s][p]*w[s]*B[s][n] ----------------
__global__ void __launch_bounds__(256) k_states() {
    int z = blockIdx.z; int d = z >> 7, c = (z >> 3) & 15, h = z & 7;
    __shared__ float Aw[16][68], Bsh[16][132];
    __shared__ float daF[256], dtF[256];
    int tid = threadIdx.x, tx = tid & 15, ty = tid >> 4;
    daF[tid] = g_dA[(size_t)(d * Lc + c * CSc + tid) * NHc + h];
    dtF[tid] = g_dt[(size_t)(d * Lc + c * CSc + tid) * NHc + h];
    __syncthreads();
    float daL = daF[255];
    const float* base = g_xBC + (size_t)(d * Lc + c * CSc) * CDc;
    float acc[4][8] = {};
    for (int s0 = 0; s0 < CSc; s0 += 16) {
        {   // X^T * w tile: Aw[s][p]
            int e = tid * 4; int col = e & 63; int ss = e >> 6;
            float w = dtF[s0 + ss] * __expf(daL - daF[s0 + ss]);
            float4 v = *(const float4*)(base + (size_t)(s0 + ss) * CDc + h * HDc + col);
            Aw[ss][col] = v.x*w; Aw[ss][col+1] = v.y*w; Aw[ss][col+2] = v.z*w; Aw[ss][col+3] = v.w*w;
        }
        #pragma unroll
        for (int hh = 0; hh < 2; hh++) {    // B tile: Bsh[s][n], 128 n
            int e = tid * 4 + hh * 1024; int col = e & 127; int ss = e >> 7;
            float4 v = *(const float4*)(base + (size_t)(s0 + ss) * CDc + DIc + col);
            Bsh[ss][col] = v.x; Bsh[ss][col+1] = v.y; Bsh[ss][col+2] = v.z; Bsh[ss][col+3] = v.w;
        }
        __syncthreads();
        fma4x8(Aw, Bsh, acc, tx, ty);
        __syncthreads();
    }
    float* out = g_st + (size_t)((d * NCc + c) * NHc + h) * HDc * DSc;
    #pragma unroll
    for (int i = 0; i < 4; i++)
        #pragma unroll
        for (int j = 0; j < 8; j++)
            out[(ty*4 + i) * DSc + tx*8 + j] = acc[i][j];
}

// ---------------- 7. inter-chunk scan ----------------
__global__ void __launch_bounds__(256) k_chunkscan() {
    int dh = blockIdx.x; int d = dh >> 3, h = dh & 7;
    int tid = threadIdx.x;
    float carry[32];
    #pragma unroll
    for (int t = 0; t < 32; t++) carry[t] = 0.f;
    for (int c = 0; c < NCc; c++) {
        float cd = __expf(g_dA[(size_t)(d * Lc + c * CSc + 255) * NHc + h]);
        size_t off = (size_t)((d * NCc + c) * NHc + h) * 8192;
        #pragma unroll
        for (int t = 0; t < 32; t++) {
            int e = tid + t * 256;
            g_pv[off + e] = carry[t];
            carry[t] = carry[t] * cd + g_st[off + e];
        }
    }
}

// ---------------- 8. y += exp(dA_i)*(C @ prev^T) + D*x ----------------
__global__ void __launch_bounds__(256) k_yoff(const float* __restrict__ D_param) {
    int i0 = blockIdx.x * 128;
    int z  = blockIdx.z; int d = z >> 7, c = (z >> 3) & 15, h = z & 7;
    __shared__ float Cs[16][132], Ps[16][68];
    __shared__ float daI[128];
    int tid = threadIdx.x, tx = tid & 15, ty = tid >> 4;
    if (tid < 128) daI[tid] = g_dA[(size_t)(d * Lc + c * CSc + i0 + tid) * NHc + h];
    const float* base = g_xBC + (size_t)(d * Lc + c * CSc) * CDc;
    const float* A = base + (size_t)i0 * CDc + (DIc + DSc);
    const float* pv = g_pv + (size_t)((d * NCc + c) * NHc + h) * HDc * DSc;
    float acc[8][4] = {};
    for (int k0 = 0; k0 < DSc; k0 += 16) {
        ld128(A, CDc, k0, Cs, tid);
        ld64 (pv, DSc, k0, Ps, tid);
        __syncthreads();
        fma8x4(Cs, Ps, acc, tx, ty);
        __syncthreads();
    }
    float Dh = D_param[d * NHc + h];
    #pragma unroll
    for (int i = 0; i < 8; i++) {
        float ei = __expf(daI[ty*8 + i]);
        int lg = c * CSc + i0 + ty*8 + i;
        #pragma unroll
        for (int j = 0; j < 4; j++) {
            int p = tx*4 + j;
            size_t yi = (size_t)(d * Lc + lg) * DIc + h * HDc + p;
            float xv = g_xBC[(size_t)(d * Lc + lg) * CDc + h * HDc + p];
            g_y[yi] = g_y[yi] + ei * acc[i][j] + Dh * xv;
        }
    }
}

// ---------------- 9. gate + RMSNorm ----------------
__global__ void __launch_bounds__(256) k_norm(const float* __restrict__ norm_w) {
    int l = blockIdx.x, d = blockIdx.y, tid = threadIdx.x;
    float v[2]; float ss = 0.f;
    #pragma unroll
    for (int t = 0; t < 2; t++) {
        int j = tid + t * 256;
        float zz = g_Z[(size_t)(d * Lc + l) * DIPc + j];
        float yy = g_y[(size_t)(d * Lc + l) * DIc + j];
        float val = yy * silu_f(zz);
        v[t] = val; ss += val * val;
    }
    __shared__ float red[256];
    red[tid] = ss; __syncthreads();
    for (int o = 128; o > 0; o >>= 1) { if (tid < o) red[tid] += red[tid + o]; __syncthreads(); }
    float scale = rsqrtf(red[0] / (float)DIc + EPSc);
    #pragma unroll
    for (int t = 0; t < 2; t++) {
        int j = tid + t * 256;
        g_y[(size_t)(d * Lc + l) * DIc + j] = v[t] * scale * norm_w[d * DIc + j];
    }
}

// ---------------- 10. out-proj + permuted scatter ----------------
__global__ void __launch_bounds__(256) k_outproj(const float* __restrict__ Wout) {
    int d = blockIdx.z;
    int m0 = blockIdx.x * 128, n0 = blockIdx.y * 128;
    const float* A = g_y + (size_t)d * Lc * DIc + (size_t)m0 * DIc;
    const float* B = Wout + (size_t)d * DMc * DIc + (size_t)n0 * DIc;
    __shared__ float As[16][132], Bs[16][132];
    int tid = threadIdx.x, tx = tid & 15, ty = tid >> 4;
    float acc[8][8] = {};
    for (int k0 = 0; k0 < DIc; k0 += 16) {
        ld128(A, DIc, k0, As, tid);
        ld128(B, DIc, k0, Bs, tid);
        __syncthreads();
        fma8x8(As, Bs, acc, tx, ty);
        __syncthreads();
    }
    #pragma unroll
    for (int i = 0; i < 8; i++) {
        int l = m0 + ty*8 + i;
        int r;
        if      (d == 0) r = l;
        else if (d == 1) r = 4095 - l;
        else if (d == 2) r = (l & 63) * 64 + (l >> 6);
        else             { int lv = 4095 - l; r = (lv & 63) * 64 + (lv >> 6); }
        #pragma unroll
        for (int j = 0; j < 8; j++)
            g_cat[(size_t)r * (4 * DMc) + d * DMc + n0 + tx*8 + j] = acc[i][j];
    }
}

// ---------------- 11. final GEMM, SiLU fused on A ----------------
__global__ void __launch_bounds__(256) k_final(const float* __restrict__ Wf,
                                               float* __restrict__ out) {
    int m0 = blockIdx.x * 128, n0 = blockIdx.y * 128;
    const float* A = g_cat + (size_t)m0 * 1024;
    const float* B = Wf + (size_t)n0 * 1024;
    __shared__ float As[16][132], Bs[16][132];
    int tid = threadIdx.x, tx = tid & 15, ty = tid >> 4;
    float acc[8][8] = {};
    for (int k0 = 0; k0 < 1024; k0 += 16) {
        ld128s(A, 1024, k0, As, tid);
        ld128 (B, 1024, k0, Bs, tid);
        __syncthreads();
        fma8x8(As, Bs, acc, tx, ty);
        __syncthreads();
    }
    #pragma unroll
    for (int i = 0; i < 8; i++)
        #pragma unroll
        for (int j = 0; j < 8; j++)
            out[(size_t)(m0 + ty*8 + i) * DMc + n0 + tx*8 + j] = acc[i][j];
}

// ---------------- launcher ----------------
extern "C" void kernel_launch(void* const* d_in, const int* in_sizes, int n_in,
                              void* d_out, int out_size) {
    const float* pts      = (const float*)d_in[0];
    const float* in_proj  = (const float*)d_in[2];
    const float* conv_w   = (const float*)d_in[3];
    const float* conv_b   = (const float*)d_in[4];
    const float* dt_bias  = (const float*)d_in[5];
    const float* A_log    = (const float*)d_in[6];
    const float* D_param  = (const float*)d_in[7];
    const float* norm_w   = (const float*)d_in[8];
    const float* outp_w   = (const float*)d_in[9];
    const float* final_w  = (const float*)d_in[10];
    float* out = (float*)d_out;

    k_buildU   <<<dim3(128, 8, 4), dim3(32, 8)>>>(pts);
    k_inproj   <<<dim3(32, 11, 4), 256>>>(in_proj);
    k_conv     <<<dim3(4096, 4),   256>>>(conv_w, conv_b, dt_bias);
    k_scan     <<<dim3(16, 8, 4),  256>>>(A_log);
    k_cb       <<<dim3(2, 2, 64),  256>>>();
    k_ydiag    <<<dim3(2, 1, 512), 256>>>();
    k_states   <<<dim3(1, 1, 512), 256>>>();
    k_chunkscan<<<32, 256>>>();
    k_yoff     <<<dim3(2, 1, 512), 256>>>(D_param);
    k_norm     <<<dim3(4096, 4),   256>>>(norm_w);
    k_outproj  <<<dim3(32, 2, 4),  256>>>(outp_w);
    k_final    <<<dim3(32, 2),     256>>>(final_w, out);
}

// round 7
// speedup vs baseline: 2.0053x; 1.8855x over previous
#include <cuda_runtime.h>
#include <math.h>

// ---------------- problem constants ----------------
#define DMc   256
#define Lc    4096
#define DSc   128
#define DIc   512
#define NHc   8
#define HDc   64
#define CDc   768
#define DIPc  1288
#define CSc   256
#define NCc   16
#define EPSc  1e-5f
#define LDT   136    // smem row pitch (136 % 32 banks = 8 -> conflict-free frags)

// ---------------- device scratch ----------------
__device__ float g_U  [4 * Lc * DMc];
__device__ float g_Z  [4 * Lc * DIPc];
__device__ float g_xBC[4 * Lc * CDc];
__device__ float g_dt [4 * Lc * NHc];
__device__ float g_dA [4 * Lc * NHc];
__device__ float g_CB [4 * NCc * CSc * CSc];
__device__ float g_y  [4 * Lc * DIc];
__device__ float g_st [4 * NCc * NHc * HDc * DSc];
__device__ float g_pv [4 * NCc * NHc * HDc * DSc];
__device__ float g_cat[Lc * 4 * DMc];

__device__ __forceinline__ float silu_f(float x) { return x / (1.f + __expf(-x)); }

// ---------------- tf32 helpers ----------------
__device__ __forceinline__ unsigned f2t(float x) {
    unsigned r; asm("cvt.rna.tf32.f32 %0, %1;" : "=r"(r) : "f"(x)); return r;
}
__device__ __forceinline__ float f2tf(float x) { return __uint_as_float(f2t(x)); }

__device__ __forceinline__ void mma_tf32(float& d0, float& d1, float& d2, float& d3,
                                         unsigned a0, unsigned a1, unsigned a2, unsigned a3,
                                         unsigned b0, unsigned b1) {
    asm volatile("mma.sync.aligned.m16n8k8.row.col.f32.tf32.tf32.f32 "
                 "{%0,%1,%2,%3}, {%4,%5,%6,%7}, {%8,%9}, {%0,%1,%2,%3};\n"
                 : "+f"(d0), "+f"(d1), "+f"(d2), "+f"(d3)
                 : "r"(a0), "r"(a1), "r"(a2), "r"(a3), "r"(b0), "r"(b1));
}

// warp computes MF*16 x NF*8 at (wm0, wn0) from k-major smem tiles (BK=16)
template<int MF, int NF>
__device__ __forceinline__ void mma_tile(const float (*As)[LDT], const float (*Bs)[LDT],
                                         float acc[MF][NF][4], int wm0, int wn0, int lane) {
    int gid = lane >> 2, t4 = lane & 3;
    #pragma unroll
    for (int ks = 0; ks < 16; ks += 8) {
        unsigned a[MF][4], b[NF][2];
        #pragma unroll
        for (int mi = 0; mi < MF; mi++) {
            int m = wm0 + mi * 16 + gid;
            a[mi][0] = __float_as_uint(As[ks + t4    ][m]);
            a[mi][1] = __float_as_uint(As[ks + t4    ][m + 8]);
            a[mi][2] = __float_as_uint(As[ks + t4 + 4][m]);
            a[mi][3] = __float_as_uint(As[ks + t4 + 4][m + 8]);
        }
        #pragma unroll
        for (int nj = 0; nj < NF; nj++) {
            int n = wn0 + nj * 8 + gid;
            b[nj][0] = __float_as_uint(Bs[ks + t4    ][n]);
            b[nj][1] = __float_as_uint(Bs[ks + t4 + 4][n]);
        }
        #pragma unroll
        for (int mi = 0; mi < MF; mi++)
            #pragma unroll
            for (int nj = 0; nj < NF; nj++)
                mma_tf32(acc[mi][nj][0], acc[mi][nj][1], acc[mi][nj][2], acc[mi][nj][3],
                         a[mi][0], a[mi][1], a[mi][2], a[mi][3], b[nj][0], b[nj][1]);
    }
}

// ======== tile loaders: BK=16, convert to tf32 on store ========
__device__ __forceinline__ void ld128(const float* __restrict__ G, int ld, int k0,
                                      float (*S)[LDT], int tid) {
    #pragma unroll
    for (int h = 0; h < 2; h++) {
        int e = tid * 4 + h * 1024; int kk = e & 15; int rr = e >> 4;
        float4 v = *(const float4*)(G + (size_t)rr * ld + k0 + kk);
        S[kk][rr] = f2tf(v.x); S[kk+1][rr] = f2tf(v.y);
        S[kk+2][rr] = f2tf(v.z); S[kk+3][rr] = f2tf(v.w);
    }
}
__device__ __forceinline__ void ld128m(const float* __restrict__ G, int ld, int k0, int rlim,
                                       float (*S)[LDT], int tid) {
    #pragma unroll
    for (int h = 0; h < 2; h++) {
        int e = tid * 4 + h * 1024; int kk = e & 15; int rr = e >> 4;
        float4 v = make_float4(0.f, 0.f, 0.f, 0.f);
        if (rr < rlim) v = *(const float4*)(G + (size_t)rr * ld + k0 + kk);
        S[kk][rr] = f2tf(v.x); S[kk+1][rr] = f2tf(v.y);
        S[kk+2][rr] = f2tf(v.z); S[kk+3][rr] = f2tf(v.w);
    }
}
__device__ __forceinline__ void ld128s(const float* __restrict__ G, int ld, int k0,
                                       float (*S)[LDT], int tid) {   // silu then tf32
    #pragma unroll
    for (int h = 0; h < 2; h++) {
        int e = tid * 4 + h * 1024; int kk = e & 15; int rr = e >> 4;
        float4 v = *(const float4*)(G + (size_t)rr * ld + k0 + kk);
        S[kk][rr] = f2tf(silu_f(v.x)); S[kk+1][rr] = f2tf(silu_f(v.y));
        S[kk+2][rr] = f2tf(silu_f(v.z)); S[kk+3][rr] = f2tf(silu_f(v.w));
    }
}
__device__ __forceinline__ void ld64(const float* __restrict__ G, int ld, int k0,
                                     float (*S)[LDT], int tid) {
    int e = tid * 4; int kk = e & 15; int rr = e >> 4;    // rr 0..63
    float4 v = *(const float4*)(G + (size_t)rr * ld + k0 + kk);
    S[kk][rr] = f2tf(v.x); S[kk+1][rr] = f2tf(v.y);
    S[kk+2][rr] = f2tf(v.z); S[kk+3][rr] = f2tf(v.w);
}

// ---------------- 0. gather + transpose ----------------
__global__ void k_buildU(const float* __restrict__ pts) {
    int d  = blockIdx.z;
    int lt = blockIdx.x * 32;
    int mt = blockIdx.y * 32;
    __shared__ float tile[32][33];
    int tx = threadIdx.x, ty = threadIdx.y;
    #pragma unroll
    for (int r = 0; r < 4; r++) {
        int i = ty + r * 8;
        int l = lt + tx;
        int lp;
        if      (d == 0) lp = l;
        else if (d == 1) lp = 4095 - l;
        else if (d == 2) lp = (l & 63) * 64 + (l >> 6);
        else             { int lv = 4095 - l; lp = (lv & 63) * 64 + (lv >> 6); }
        tile[i][tx] = pts[(mt + i) * Lc + lp];
    }
    __syncthreads();
    #pragma unroll
    for (int r = 0; r < 4; r++) {
        int i = ty + r * 8;
        g_U[(size_t)(d * Lc + lt + i) * DMc + mt + tx] = tile[tx][i];
    }
}

// ---------------- 1. in-proj: Z = U(4096x256) @ Win(1288x256)^T ----------------
__global__ void __launch_bounds__(256) k_inproj(const float* __restrict__ Win) {
    int d = blockIdx.z;
    int m0 = blockIdx.x * 128, n0 = blockIdx.y * 128;
    const float* A = g_U + (size_t)d * Lc * DMc + (size_t)m0 * DMc;
    const float* B = Win + (size_t)d * DIPc * DMc + (size_t)n0 * DMc;
    int nrem = DIPc - n0;
    __shared__ float As[16][LDT], Bs[16][LDT];
    int tid = threadIdx.x, wid = tid >> 5, lane = tid & 31;
    int wm0 = (wid & 1) * 64, wn0 = (wid >> 1) * 32;
    float acc[4][4][4] = {};
    for (int k0 = 0; k0 < DMc; k0 += 16) {
        ld128 (A, DMc, k0, As, tid);
        ld128m(B, DMc, k0, nrem, Bs, tid);
        __syncthreads();
        mma_tile<4,4>(As, Bs, acc, wm0, wn0, lane);
        __syncthreads();
    }
    int gid = lane >> 2, t4 = lane & 3;
    #pragma unroll
    for (int mi = 0; mi < 4; mi++) {
        int r0 = m0 + wm0 + mi * 16 + gid, r1 = r0 + 8;
        #pragma unroll
        for (int nj = 0; nj < 4; nj++) {
            int c0 = n0 + wn0 + nj * 8 + t4 * 2;
            if (c0 < DIPc) {
                g_Z[(size_t)(d * Lc + r0) * DIPc + c0]     = acc[mi][nj][0];
                g_Z[(size_t)(d * Lc + r0) * DIPc + c0 + 1] = acc[mi][nj][1];
                g_Z[(size_t)(d * Lc + r1) * DIPc + c0]     = acc[mi][nj][2];
                g_Z[(size_t)(d * Lc + r1) * DIPc + c0 + 1] = acc[mi][nj][3];
            }
        }
    }
}

// ---------------- 2. conv1d + silu ; softplus dt ----------------
__global__ void __launch_bounds__(256) k_conv(const float* __restrict__ conv_w,
                                              const float* __restrict__ conv_b,
                                              const float* __restrict__ dt_bias) {
    int l = blockIdx.x, d = blockIdx.y, tid = threadIdx.x;
    for (int ch = tid; ch < CDc; ch += 256) {
        float acc = conv_b[d * CDc + ch];
        const float* cw = conv_w + (size_t)(d * CDc + ch) * 4;
        #pragma unroll
        for (int w = 0; w < 4; w++) {
            int ls = l - 3 + w;
            if (ls >= 0)
                acc += g_Z[(size_t)(d * Lc + ls) * DIPc + DIc + ch] * cw[w];
        }
        g_xBC[(size_t)(d * Lc + l) * CDc + ch] = silu_f(acc);
    }
    if (tid < NHc) {
        float v = g_Z[(size_t)(d * Lc + l) * DIPc + (DIc + CDc) + tid] + dt_bias[d * NHc + tid];
        float sp = (v > 20.f) ? v : log1pf(__expf(v));
        g_dt[(size_t)(d * Lc + l) * NHc + tid] = sp;
    }
}

// ---------------- 3. per-chunk cumsum of dt*A ----------------
__global__ void __launch_bounds__(256) k_scan(const float* __restrict__ A_log) {
    int c = blockIdx.x, h = blockIdx.y, d = blockIdx.z, s = threadIdx.x;
    float A = -__expf(A_log[d * NHc + h]);
    __shared__ float buf[256];
    buf[s] = g_dt[(size_t)(d * Lc + c * CSc + s) * NHc + h] * A;
    __syncthreads();
    for (int off = 1; off < 256; off <<= 1) {
        float t = (s >= off) ? buf[s - off] : 0.f;
        __syncthreads();
        buf[s] += t;
        __syncthreads();
    }
    g_dA[(size_t)(d * Lc + c * CSc + s) * NHc + h] = buf[s];
}

// ---------------- 4. CB = C @ B^T  (256x256, K=128) ----------------
__global__ void __launch_bounds__(256) k_cb() {
    int dc = blockIdx.z; int d = dc >> 4, c = dc & 15;
    int i0 = blockIdx.x * 128, j0 = blockIdx.y * 128;
    const float* base = g_xBC + (size_t)(d * Lc + c * CSc) * CDc;
    const float* A = base + (size_t)i0 * CDc + (DIc + DSc);
    const float* B = base + (size_t)j0 * CDc + DIc;
    __shared__ float As[16][LDT], Bs[16][LDT];
    int tid = threadIdx.x, wid = tid >> 5, lane = tid & 31;
    int wm0 = (wid & 1) * 64, wn0 = (wid >> 1) * 32;
    float acc[4][4][4] = {};
    for (int k0 = 0; k0 < DSc; k0 += 16) {
        ld128(A, CDc, k0, As, tid);
        ld128(B, CDc, k0, Bs, tid);
        __syncthreads();
        mma_tile<4,4>(As, Bs, acc, wm0, wn0, lane);
        __syncthreads();
    }
    float* out = g_CB + (size_t)(d * NCc + c) * CSc * CSc;
    int gid = lane >> 2, t4 = lane & 3;
    #pragma unroll
    for (int mi = 0; mi < 4; mi++) {
        int r0 = i0 + wm0 + mi * 16 + gid, r1 = r0 + 8;
        #pragma unroll
        for (int nj = 0; nj < 4; nj++) {
            int c0 = j0 + wn0 + nj * 8 + t4 * 2;
            out[r0 * CSc + c0]     = acc[mi][nj][0];
            out[r0 * CSc + c0 + 1] = acc[mi][nj][1];
            out[r1 * CSc + c0]     = acc[mi][nj][2];
            out[r1 * CSc + c0 + 1] = acc[mi][nj][3];
        }
    }
}

// ---------------- 5. y_diag = (CB.mask.exp(dAi-dAj).dt_j) @ X ----------------
__global__ void __launch_bounds__(256) k_ydiag() {
    int i0 = blockIdx.x * 128;
    int z  = blockIdx.z; int d = z >> 7, c = (z >> 3) & 15, h = z & 7;
    __shared__ float Ss[16][LDT], Xs[16][LDT];
    __shared__ float daF[256], dtF[256];
    int tid = threadIdx.x, wid = tid >> 5, lane = tid & 31;
    int wm0 = (wid & 3) * 32, wn0 = (wid >> 2) * 32;
    daF[tid] = g_dA[(size_t)(d * Lc + c * CSc + tid) * NHc + h];
    dtF[tid] = g_dt[(size_t)(d * Lc + c * CSc + tid) * NHc + h];
    __syncthreads();
    const float* cbb   = g_CB + (size_t)(d * NCc + c) * CSc * CSc;
    const float* xbase = g_xBC + (size_t)(d * Lc + c * CSc) * CDc + h * HDc;
    float acc[2][4][4] = {};
    for (int j0 = 0; j0 < CSc; j0 += 16) {
        #pragma unroll
        for (int hh = 0; hh < 2; hh++) {    // score tile Ss[j][i]
            int e = tid * 4 + hh * 1024; int kk = e & 15; int ii = e >> 4;
            float4 v = *(const float4*)(cbb + (i0 + ii) * CSc + j0 + kk);
            float r[4] = {v.x, v.y, v.z, v.w};
            float dai = daF[i0 + ii];
            int ig = i0 + ii;
            #pragma unroll
            for (int q = 0; q < 4; q++) {
                int jg = j0 + kk + q;
                float sv = 0.f;
                if (jg <= ig) sv = r[q] * __expf(dai - daF[jg]) * dtF[jg];
                Ss[kk + q][ii] = f2tf(sv);
            }
        }
        {   // X tile Xs[j][p]
            int e = tid * 4; int p = e & 63; int jj = e >> 6;
            float4 v = *(const float4*)(xbase + (size_t)(j0 + jj) * CDc + p);
            Xs[jj][p] = f2tf(v.x); Xs[jj][p+1] = f2tf(v.y);
            Xs[jj][p+2] = f2tf(v.z); Xs[jj][p+3] = f2tf(v.w);
        }
        __syncthreads();
        mma_tile<2,4>(Ss, Xs, acc, wm0, wn0, lane);
        __syncthreads();
    }
    int gid = lane >> 2, t4 = lane & 3;
    #pragma unroll
    for (int mi = 0; mi < 2; mi++) {
        int lr0 = wm0 + mi * 16 + gid, lr1 = lr0 + 8;
        size_t y0 = (size_t)(d * Lc + c * CSc + i0 + lr0) * DIc + h * HDc;
        size_t y1 = (size_t)(d * Lc + c * CSc + i0 + lr1) * DIc + h * HDc;
        #pragma unroll
        for (int nj = 0; nj < 4; nj++) {
            int p0 = wn0 + nj * 8 + t4 * 2;
            g_y[y0 + p0]     = acc[mi][nj][0];
            g_y[y0 + p0 + 1] = acc[mi][nj][1];
            g_y[y1 + p0]     = acc[mi][nj][2];
            g_y[y1 + p0 + 1] = acc[mi][nj][3];
        }
    }
}

// ---------------- 6. states[p][n] = sum_s X[s][p]*w[s]*B[s][n] ----------------
__global__ void __launch_bounds__(256) k_states() {
    int z = blockIdx.z; int d = z >> 7, c = (z >> 3) & 15, h = z & 7;
    __shared__ float Aw[16][LDT], Bsh[16][LDT];
    __shared__ float daF[256], dtF[256];
    int tid = threadIdx.x, wid = tid >> 5, lane = tid & 31;
    int wm0 = (wid & 1) * 32, wn0 = (wid >> 1) * 32;
    daF[tid] = g_dA[(size_t)(d * Lc + c * CSc + tid) * NHc + h];
    dtF[tid] = g_dt[(size_t)(d * Lc + c * CSc + tid) * NHc + h];
    __syncthreads();
    float daL = daF[255];
    const float* base = g_xBC + (size_t)(d * Lc + c * CSc) * CDc;
    float acc[2][4][4] = {};
    for (int s0 = 0; s0 < CSc; s0 += 16) {
        {   // X^T * w tile: Aw[s][p]
            int e = tid * 4; int col = e & 63; int ss = e >> 6;
            float w = dtF[s0 + ss] * __expf(daL - daF[s0 + ss]);
            float4 v = *(const float4*)(base + (size_t)(s0 + ss) * CDc + h * HDc + col);
            Aw[ss][col] = f2tf(v.x*w); Aw[ss][col+1] = f2tf(v.y*w);
            Aw[ss][col+2] = f2tf(v.z*w); Aw[ss][col+3] = f2tf(v.w*w);
        }
        #pragma unroll
        for (int hh = 0; hh < 2; hh++) {    // B tile: Bsh[s][n], 128 n
            int e = tid * 4 + hh * 1024; int col = e & 127; int ss = e >> 7;
            float4 v = *(const float4*)(base + (size_t)(s0 + ss) * CDc + DIc + col);
            Bsh[ss][col] = f2tf(v.x); Bsh[ss][col+1] = f2tf(v.y);
            Bsh[ss][col+2] = f2tf(v.z); Bsh[ss][col+3] = f2tf(v.w);
        }
        __syncthreads();
        mma_tile<2,4>(Aw, Bsh, acc, wm0, wn0, lane);
        __syncthreads();
    }
    float* out = g_st + (size_t)((d * NCc + c) * NHc + h) * HDc * DSc;
    int gid = lane >> 2, t4 = lane & 3;
    #pragma unroll
    for (int mi = 0; mi < 2; mi++) {
        int r0 = wm0 + mi * 16 + gid, r1 = r0 + 8;
        #pragma unroll
        for (int nj = 0; nj < 4; nj++) {
            int c0 = wn0 + nj * 8 + t4 * 2;
            out[r0 * DSc + c0]     = acc[mi][nj][0];
            out[r0 * DSc + c0 + 1] = acc[mi][nj][1];
            out[r1 * DSc + c0]     = acc[mi][nj][2];
            out[r1 * DSc + c0 + 1] = acc[mi][nj][3];
        }
    }
}

// ---------------- 7. inter-chunk scan ----------------
__global__ void __launch_bounds__(256) k_chunkscan() {
    int dh = blockIdx.x; int d = dh >> 3, h = dh & 7;
    int tid = threadIdx.x;
    float carry[32];
    #pragma unroll
    for (int t = 0; t < 32; t++) carry[t] = 0.f;
    for (int c = 0; c < NCc; c++) {
        float cd = __expf(g_dA[(size_t)(d * Lc + c * CSc + 255) * NHc + h]);
        size_t off = (size_t)((d * NCc + c) * NHc + h) * 8192;
        #pragma unroll
        for (int t = 0; t < 32; t++) {
            int e = tid + t * 256;
            g_pv[off + e] = carry[t];
            carry[t] = carry[t] * cd + g_st[off + e];
        }
    }
}

// ---------------- 8. y += exp(dA_i)*(C @ prev^T) + D*x ----------------
__global__ void __launch_bounds__(256) k_yoff(const float* __restrict__ D_param) {
    int i0 = blockIdx.x * 128;
    int z  = blockIdx.z; int d = z >> 7, c = (z >> 3) & 15, h = z & 7;
    __shared__ float Cs[16][LDT], Ps[16][LDT];
    __shared__ float daI[128];
    int tid = threadIdx.x, wid = tid >> 5, lane = tid & 31;
    int wm0 = (wid & 3) * 32, wn0 = (wid >> 2) * 32;
    if (tid < 128) daI[tid] = g_dA[(size_t)(d * Lc + c * CSc + i0 + tid) * NHc + h];
    const float* base = g_xBC + (size_t)(d * Lc + c * CSc) * CDc;
    const float* A = base + (size_t)i0 * CDc + (DIc + DSc);
    const float* pv = g_pv + (size_t)((d * NCc + c) * NHc + h) * HDc * DSc;
    float acc[2][4][4] = {};
    for (int k0 = 0; k0 < DSc; k0 += 16) {
        ld128(A, CDc, k0, Cs, tid);
        ld64 (pv, DSc, k0, Ps, tid);
        __syncthreads();
        mma_tile<2,4>(Cs, Ps, acc, wm0, wn0, lane);
        __syncthreads();
    }
    float Dh = D_param[d * NHc + h];
    int gid = lane >> 2, t4 = lane & 3;
    #pragma unroll
    for (int mi = 0; mi < 2; mi++) {
        int lr0 = wm0 + mi * 16 + gid, lr1 = lr0 + 8;
        float e0 = __expf(daI[lr0]), e1 = __expf(daI[lr1]);
        int l0 = c * CSc + i0 + lr0, l1 = c * CSc + i0 + lr1;
        #pragma unroll
        for (int nj = 0; nj < 4; nj++) {
            int p0 = wn0 + nj * 8 + t4 * 2;
            size_t y0 = (size_t)(d * Lc + l0) * DIc + h * HDc + p0;
            size_t y1 = (size_t)(d * Lc + l1) * DIc + h * HDc + p0;
            size_t x0 = (size_t)(d * Lc + l0) * CDc + h * HDc + p0;
            size_t x1 = (size_t)(d * Lc + l1) * CDc + h * HDc + p0;
            g_y[y0]     += e0 * acc[mi][nj][0] + Dh * g_xBC[x0];
            g_y[y0 + 1] += e0 * acc[mi][nj][1] + Dh * g_xBC[x0 + 1];
            g_y[y1]     += e1 * acc[mi][nj][2] + Dh * g_xBC[x1];
            g_y[y1 + 1] += e1 * acc[mi][nj][3] + Dh * g_xBC[x1 + 1];
        }
    }
}

// ---------------- 9. gate + RMSNorm ----------------
__global__ void __launch_bounds__(256) k_norm(const float* __restrict__ norm_w) {
    int l = blockIdx.x, d = blockIdx.y, tid = threadIdx.x;
    float v[2]; float ss = 0.f;
    #pragma unroll
    for (int t = 0; t < 2; t++) {
        int j = tid + t * 256;
        float zz = g_Z[(size_t)(d * Lc + l) * DIPc + j];
        float yy = g_y[(size_t)(d * Lc + l) * DIc + j];
        float val = yy * silu_f(zz);
        v[t] = val; ss += val * val;
    }
    __shared__ float red[256];
    red[tid] = ss; __syncthreads();
    for (int o = 128; o > 0; o >>= 1) { if (tid < o) red[tid] += red[tid + o]; __syncthreads(); }
    float scale = rsqrtf(red[0] / (float)DIc + EPSc);
    #pragma unroll
    for (int t = 0; t < 2; t++) {
        int j = tid + t * 256;
        g_y[(size_t)(d * Lc + l) * DIc + j] = v[t] * scale * norm_w[d * DIc + j];
    }
}

// ---------------- 10. out-proj + permuted scatter ----------------
__global__ void __launch_bounds__(256) k_outproj(const float* __restrict__ Wout) {
    int d = blockIdx.z;
    int m0 = blockIdx.x * 128, n0 = blockIdx.y * 128;
    const float* A = g_y + (size_t)d * Lc * DIc + (size_t)m0 * DIc;
    const float* B = Wout + (size_t)d * DMc * DIc + (size_t)n0 * DIc;
    __shared__ float As[16][LDT], Bs[16][LDT];
    int tid = threadIdx.x, wid = tid >> 5, lane = tid & 31;
    int wm0 = (wid & 1) * 64, wn0 = (wid >> 1) * 32;
    float acc[4][4][4] = {};
    for (int k0 = 0; k0 < DIc; k0 += 16) {
        ld128(A, DIc, k0, As, tid);
        ld128(B, DIc, k0, Bs, tid);
        __syncthreads();
        mma_tile<4,4>(As, Bs, acc, wm0, wn0, lane);
        __syncthreads();
    }
    int gid = lane >> 2, t4 = lane & 3;
    #pragma unroll
    for (int mi = 0; mi < 4; mi++) {
        #pragma unroll
        for (int half = 0; half < 2; half++) {
            int l = m0 + wm0 + mi * 16 + gid + half * 8;
            int r;
            if      (d == 0) r = l;
            else if (d == 1) r = 4095 - l;
            else if (d == 2) r = (l & 63) * 64 + (l >> 6);
            else             { int lv = 4095 - l; r = (lv & 63) * 64 + (lv >> 6); }
            #pragma unroll
            for (int nj = 0; nj < 4; nj++) {
                int c0 = n0 + wn0 + nj * 8 + t4 * 2;
                g_cat[(size_t)r * (4 * DMc) + d * DMc + c0]     = acc[mi][nj][half * 2];
                g_cat[(size_t)r * (4 * DMc) + d * DMc + c0 + 1] = acc[mi][nj][half * 2 + 1];
            }
        }
    }
}

// ---------------- 11. final GEMM (128x64 tiles), SiLU fused on A ----------------
__global__ void __launch_bounds__(256) k_final(const float* __restrict__ Wf,
                                               float* __restrict__ out) {
    int m0 = blockIdx.x * 128, n0 = blockIdx.y * 64;
    const float* A = g_cat + (size_t)m0 * 1024;
    const float* B = Wf + (size_t)n0 * 1024;
    __shared__ float As[16][LDT], Bs[16][LDT];
    int tid = threadIdx.x, wid = tid >> 5, lane = tid & 31;
    int wm0 = (wid & 3) * 32, wn0 = (wid >> 2) * 32;
    float acc[2][4][4] = {};
    for (int k0 = 0; k0 < 1024; k0 += 16) {
        ld128s(A, 1024, k0, As, tid);
        ld64  (B, 1024, k0, Bs, tid);
        __syncthreads();
        mma_tile<2,4>(As, Bs, acc, wm0, wn0, lane);
        __syncthreads();
    }
    int gid = lane >> 2, t4 = lane & 3;
    #pragma unroll
    for (int mi = 0; mi < 2; mi++) {
        int r0 = m0 + wm0 + mi * 16 + gid, r1 = r0 + 8;
        #pragma unroll
        for (int nj = 0; nj < 4; nj++) {
            int c0 = n0 + wn0 + nj * 8 + t4 * 2;
            out[(size_t)r0 * DMc + c0]     = acc[mi][nj][0];
            out[(size_t)r0 * DMc + c0 + 1] = acc[mi][nj][1];
            out[(size_t)r1 * DMc + c0]     = acc[mi][nj][2];
            out[(size_t)r1 * DMc + c0 + 1] = acc[mi][nj][3];
        }
    }
}

// ---------------- launcher ----------------
extern "C" void kernel_launch(void* const* d_in, const int* in_sizes, int n_in,
                              void* d_out, int out_size) {
    const float* pts      = (const float*)d_in[0];
    const float* in_proj  = (const float*)d_in[2];
    const float* conv_w   = (const float*)d_in[3];
    const float* conv_b   = (const float*)d_in[4];
    const float* dt_bias  = (const float*)d_in[5];
    const float* A_log    = (const float*)d_in[6];
    const float* D_param  = (const float*)d_in[7];
    const float* norm_w   = (const float*)d_in[8];
    const float* outp_w   = (const float*)d_in[9];
    const float* final_w  = (const float*)d_in[10];
    float* out = (float*)d_out;

    k_buildU   <<<dim3(128, 8, 4), dim3(32, 8)>>>(pts);
    k_inproj   <<<dim3(32, 11, 4), 256>>>(in_proj);
    k_conv     <<<dim3(4096, 4),   256>>>(conv_w, conv_b, dt_bias);
    k_scan     <<<dim3(16, 8, 4),  256>>>(A_log);
    k_cb       <<<dim3(2, 2, 64),  256>>>();
    k_ydiag    <<<dim3(2, 1, 512), 256>>>();
    k_states   <<<dim3(1, 1, 512), 256>>>();
    k_chunkscan<<<32, 256>>>();
    k_yoff     <<<dim3(2, 1, 512), 256>>>(D_param);
    k_norm     <<<dim3(4096, 4),   256>>>(norm_w);
    k_outproj  <<<dim3(32, 2, 4),  256>>>(outp_w);
    k_final    <<<dim3(32, 4),     256>>>(final_w, out);
}

// round 13
// speedup vs baseline: 2.2343x; 1.1142x over previous
#include <cuda_runtime.h>
#include <math.h>

// ---------------- problem constants ----------------
#define DMc   256
#define Lc    4096
#define DSc   128
#define DIc   512
#define NHc   8
#define HDc   64
#define CDc   768
#define DIPc  1288
#define CSc   256
#define NCc   16
#define EPSc  1e-5f
#define LDT   136    // smem row pitch -> conflict-free tf32 fragment loads

// ---------------- device scratch ----------------
__device__ float g_U  [4 * Lc * DMc];
__device__ float g_Z  [4 * Lc * DIPc];
__device__ float g_xBC[4 * Lc * CDc];
__device__ float g_dt [4 * Lc * NHc];
__device__ float g_dA [4 * Lc * NHc];
__device__ float g_CB [4 * NCc * CSc * CSc];
__device__ float g_y  [4 * Lc * DIc];
__device__ float g_st [4 * NCc * NHc * HDc * DSc];
__device__ float g_pv [4 * NCc * NHc * HDc * DSc];
__device__ float g_cat[Lc * 4 * DMc];

__device__ __forceinline__ float silu_f(float x) { return x / (1.f + __expf(-x)); }

// ---------------- tf32 helpers ----------------
__device__ __forceinline__ unsigned f2t(float x) {
    unsigned r; asm("cvt.rna.tf32.f32 %0, %1;" : "=r"(r) : "f"(x)); return r;
}
__device__ __forceinline__ float f2tf(float x) { return __uint_as_float(f2t(x)); }

__device__ __forceinline__ void mma_tf32(float& d0, float& d1, float& d2, float& d3,
                                         unsigned a0, unsigned a1, unsigned a2, unsigned a3,
                                         unsigned b0, unsigned b1) {
    asm volatile("mma.sync.aligned.m16n8k8.row.col.f32.tf32.tf32.f32 "
                 "{%0,%1,%2,%3}, {%4,%5,%6,%7}, {%8,%9}, {%0,%1,%2,%3};\n"
                 : "+f"(d0), "+f"(d1), "+f"(d2), "+f"(d3)
                 : "r"(a0), "r"(a1), "r"(a2), "r"(a3), "r"(b0), "r"(b1));
}

template<int MF, int NF>
__device__ __forceinline__ void mma_tile(const float (*As)[LDT], const float (*Bs)[LDT],
                                         float acc[MF][NF][4], int wm0, int wn0, int lane) {
    int gid = lane >> 2, t4 = lane & 3;
    #pragma unroll
    for (int ks = 0; ks < 16; ks += 8) {
        unsigned a[MF][4], b[NF][2];
        #pragma unroll
        for (int mi = 0; mi < MF; mi++) {
            int m = wm0 + mi * 16 + gid;
            a[mi][0] = __float_as_uint(As[ks + t4    ][m]);
            a[mi][1] = __float_as_uint(As[ks + t4    ][m + 8]);
            a[mi][2] = __float_as_uint(As[ks + t4 + 4][m]);
            a[mi][3] = __float_as_uint(As[ks + t4 + 4][m + 8]);
        }
        #pragma unroll
        for (int nj = 0; nj < NF; nj++) {
            int n = wn0 + nj * 8 + gid;
            b[nj][0] = __float_as_uint(Bs[ks + t4    ][n]);
            b[nj][1] = __float_as_uint(Bs[ks + t4 + 4][n]);
        }
        #pragma unroll
        for (int mi = 0; mi < MF; mi++)
            #pragma unroll
            for (int nj = 0; nj < NF; nj++)
                mma_tf32(acc[mi][nj][0], acc[mi][nj][1], acc[mi][nj][2], acc[mi][nj][3],
                         a[mi][0], a[mi][1], a[mi][2], a[mi][3], b[nj][0], b[nj][1]);
    }
}

// ======== register-staged fetch / smem store (BK=16) ========
__device__ __forceinline__ void fetch128(const float* __restrict__ G, int ld, int k0,
                                         float4 r[2], int tid) {
    #pragma unroll
    for (int h = 0; h < 2; h++) {
        int e = tid * 4 + h * 1024; int kk = e & 15; int rr = e >> 4;
        r[h] = *(const float4*)(G + (size_t)rr * ld + k0 + kk);
    }
}
__device__ __forceinline__ void fetch128m(const float* __restrict__ G, int ld, int k0, int rlim,
                                          float4 r[2], int tid) {
    #pragma unroll
    for (int h = 0; h < 2; h++) {
        int e = tid * 4 + h * 1024; int kk = e & 15; int rr = e >> 4;
        r[h] = make_float4(0.f, 0.f, 0.f, 0.f);
        if (rr < rlim) r[h] = *(const float4*)(G + (size_t)rr * ld + k0 + kk);
    }
}
__device__ __forceinline__ void store128(const float4 r[2], float (*S)[LDT], int tid) {
    #pragma unroll
    for (int h = 0; h < 2; h++) {
        int e = tid * 4 + h * 1024; int kk = e & 15; int rr = e >> 4;
        S[kk][rr] = f2tf(r[h].x); S[kk+1][rr] = f2tf(r[h].y);
        S[kk+2][rr] = f2tf(r[h].z); S[kk+3][rr] = f2tf(r[h].w);
    }
}
__device__ __forceinline__ void store128s(const float4 r[2], float (*S)[LDT], int tid) { // silu
    #pragma unroll
    for (int h = 0; h < 2; h++) {
        int e = tid * 4 + h * 1024; int kk = e & 15; int rr = e >> 4;
        S[kk][rr] = f2tf(silu_f(r[h].x)); S[kk+1][rr] = f2tf(silu_f(r[h].y));
        S[kk+2][rr] = f2tf(silu_f(r[h].z)); S[kk+3][rr] = f2tf(silu_f(r[h].w));
    }
}
__device__ __forceinline__ void fetch64(const float* __restrict__ G, int ld, int k0,
                                        float4& r, int tid) {
    int e = tid * 4; int kk = e & 15; int rr = e >> 4;
    r = *(const float4*)(G + (size_t)rr * ld + k0 + kk);
}
__device__ __forceinline__ void store64(const float4 r, float (*S)[LDT], int tid) {
    int e = tid * 4; int kk = e & 15; int rr = e >> 4;
    S[kk][rr] = f2tf(r.x); S[kk+1][rr] = f2tf(r.y);
    S[kk+2][rr] = f2tf(r.z); S[kk+3][rr] = f2tf(r.w);
}

// ---------------- 0. gather + transpose ----------------
__global__ void k_buildU(const float* __restrict__ pts) {
    int d  = blockIdx.z;
    int lt = blockIdx.x * 32;
    int mt = blockIdx.y * 32;
    __shared__ float tile[32][33];
    int tx = threadIdx.x, ty = threadIdx.y;
    #pragma unroll
    for (int r = 0; r < 4; r++) {
        int i = ty + r * 8;
        int l = lt + tx;
        int lp;
        if      (d == 0) lp = l;
        else if (d == 1) lp = 4095 - l;
        else if (d == 2) lp = (l & 63) * 64 + (l >> 6);
        else             { int lv = 4095 - l; lp = (lv & 63) * 64 + (lv >> 6); }
        tile[i][tx] = pts[(mt + i) * Lc + lp];
    }
    __syncthreads();
    #pragma unroll
    for (int r = 0; r < 4; r++) {
        int i = ty + r * 8;
        g_U[(size_t)(d * Lc + lt + i) * DMc + mt + tx] = tile[tx][i];
    }
}

// ---------------- 1. in-proj (double-buffered) ----------------
__global__ void __launch_bounds__(256) k_inproj(const float* __restrict__ Win) {
    int d = blockIdx.z;
    int m0 = blockIdx.x * 128, n0 = blockIdx.y * 128;
    const float* A = g_U + (size_t)d * Lc * DMc + (size_t)m0 * DMc;
    const float* B = Win + (size_t)d * DIPc * DMc + (size_t)n0 * DMc;
    int nrem = DIPc - n0;
    __shared__ float As[2][16][LDT], Bs[2][16][LDT];
    int tid = threadIdx.x, wid = tid >> 5, lane = tid & 31;
    int wm0 = (wid & 1) * 64, wn0 = (wid >> 1) * 32;
    float acc[4][4][4] = {};
    float4 ra[2], rb[2];
    fetch128 (A, DMc, 0, ra, tid);
    fetch128m(B, DMc, 0, nrem, rb, tid);
    store128(ra, As[0], tid); store128(rb, Bs[0], tid);
    __syncthreads();
    const int NT = DMc / 16;
    for (int t = 0; t < NT; t++) {
        int cur = t & 1;
        if (t + 1 < NT) {
            fetch128 (A, DMc, (t + 1) * 16, ra, tid);
            fetch128m(B, DMc, (t + 1) * 16, nrem, rb, tid);
        }
        mma_tile<4,4>(As[cur], Bs[cur], acc, wm0, wn0, lane);
        if (t + 1 < NT) { store128(ra, As[cur ^ 1], tid); store128(rb, Bs[cur ^ 1], tid); }
        __syncthreads();
    }
    int gid = lane >> 2, t4 = lane & 3;
    #pragma unroll
    for (int mi = 0; mi < 4; mi++) {
        int r0 = m0 + wm0 + mi * 16 + gid, r1 = r0 + 8;
        #pragma unroll
        for (int nj = 0; nj < 4; nj++) {
            int c0 = n0 + wn0 + nj * 8 + t4 * 2;
            if (c0 < DIPc) {
                g_Z[(size_t)(d * Lc + r0) * DIPc + c0]     = acc[mi][nj][0];
                g_Z[(size_t)(d * Lc + r0) * DIPc + c0 + 1] = acc[mi][nj][1];
                g_Z[(size_t)(d * Lc + r1) * DIPc + c0]     = acc[mi][nj][2];
                g_Z[(size_t)(d * Lc + r1) * DIPc + c0 + 1] = acc[mi][nj][3];
            }
        }
    }
}

// ---------------- 2. conv1d + silu ; softplus dt ----------------
__global__ void __launch_bounds__(256) k_conv(const float* __restrict__ conv_w,
                                              const float* __restrict__ conv_b,
                                              const float* __restrict__ dt_bias) {
    int l = blockIdx.x, d = blockIdx.y, tid = threadIdx.x;
    for (int ch = tid; ch < CDc; ch += 256) {
        float acc = conv_b[d * CDc + ch];
        const float* cw = conv_w + (size_t)(d * CDc + ch) * 4;
        #pragma unroll
        for (int w = 0; w < 4; w++) {
            int ls = l - 3 + w;
            if (ls >= 0)
                acc += g_Z[(size_t)(d * Lc + ls) * DIPc + DIc + ch] * cw[w];
        }
        g_xBC[(size_t)(d * Lc + l) * CDc + ch] = silu_f(acc);
    }
    if (tid < NHc) {
        float v = g_Z[(size_t)(d * Lc + l) * DIPc + (DIc + CDc) + tid] + dt_bias[d * NHc + tid];
        float sp = (v > 20.f) ? v : log1pf(__expf(v));
        g_dt[(size_t)(d * Lc + l) * NHc + tid] = sp;
    }
}

// ---------------- 3. per-chunk cumsum of dt*A ----------------
__global__ void __launch_bounds__(256) k_scan(const float* __restrict__ A_log) {
    int c = blockIdx.x, h = blockIdx.y, d = blockIdx.z, s = threadIdx.x;
    float A = -__expf(A_log[d * NHc + h]);
    __shared__ float buf[256];
    buf[s] = g_dt[(size_t)(d * Lc + c * CSc + s) * NHc + h] * A;
    __syncthreads();
    for (int off = 1; off < 256; off <<= 1) {
        float t = (s >= off) ? buf[s - off] : 0.f;
        __syncthreads();
        buf[s] += t;
        __syncthreads();
    }
    g_dA[(size_t)(d * Lc + c * CSc + s) * NHc + h] = buf[s];
}

// ---------------- 4. CB = C @ B^T (double-buffered) ----------------
__global__ void __launch_bounds__(256) k_cb() {
    int dc = blockIdx.z; int d = dc >> 4, c = dc & 15;
    int i0 = blockIdx.x * 128, j0 = blockIdx.y * 128;
    const float* base = g_xBC + (size_t)(d * Lc + c * CSc) * CDc;
    const float* A = base + (size_t)i0 * CDc + (DIc + DSc);
    const float* B = base + (size_t)j0 * CDc + DIc;
    __shared__ float As[2][16][LDT], Bs[2][16][LDT];
    int tid = threadIdx.x, wid = tid >> 5, lane = tid & 31;
    int wm0 = (wid & 1) * 64, wn0 = (wid >> 1) * 32;
    float acc[4][4][4] = {};
    float4 ra[2], rb[2];
    fetch128(A, CDc, 0, ra, tid); fetch128(B, CDc, 0, rb, tid);
    store128(ra, As[0], tid); store128(rb, Bs[0], tid);
    __syncthreads();
    const int NT = DSc / 16;
    for (int t = 0; t < NT; t++) {
        int cur = t & 1;
        if (t + 1 < NT) {
            fetch128(A, CDc, (t + 1) * 16, ra, tid);
            fetch128(B, CDc, (t + 1) * 16, rb, tid);
        }
        mma_tile<4,4>(As[cur], Bs[cur], acc, wm0, wn0, lane);
        if (t + 1 < NT) { store128(ra, As[cur ^ 1], tid); store128(rb, Bs[cur ^ 1], tid); }
        __syncthreads();
    }
    float* out = g_CB + (size_t)(d * NCc + c) * CSc * CSc;
    int gid = lane >> 2, t4 = lane & 3;
    #pragma unroll
    for (int mi = 0; mi < 4; mi++) {
        int r0 = i0 + wm0 + mi * 16 + gid, r1 = r0 + 8;
        #pragma unroll
        for (int nj = 0; nj < 4; nj++) {
            int c0 = j0 + wn0 + nj * 8 + t4 * 2;
            out[r0 * CSc + c0]     = acc[mi][nj][0];
            out[r0 * CSc + c0 + 1] = acc[mi][nj][1];
            out[r1 * CSc + c0]     = acc[mi][nj][2];
            out[r1 * CSc + c0 + 1] = acc[mi][nj][3];
        }
    }
}

// ---------------- 5. states[p][n] ----------------
__global__ void __launch_bounds__(256) k_states() {
    int z = blockIdx.z; int d = z >> 7, c = (z >> 3) & 15, h = z & 7;
    __shared__ float Aw[16][LDT], Bsh[16][LDT];
    __shared__ float daF[256], dtF[256];
    int tid = threadIdx.x, wid = tid >> 5, lane = tid & 31;
    int wm0 = (wid & 1) * 32, wn0 = (wid >> 1) * 32;
    daF[tid] = g_dA[(size_t)(d * Lc + c * CSc + tid) * NHc + h];
    dtF[tid] = g_dt[(size_t)(d * Lc + c * CSc + tid) * NHc + h];
    __syncthreads();
    float daL = daF[255];
    const float* base = g_xBC + (size_t)(d * Lc + c * CSc) * CDc;
    float acc[2][4][4] = {};
    for (int s0 = 0; s0 < CSc; s0 += 16) {
        {
            int e = tid * 4; int col = e & 63; int ss = e >> 6;
            float w = dtF[s0 + ss] * __expf(daL - daF[s0 + ss]);
            float4 v = *(const float4*)(base + (size_t)(s0 + ss) * CDc + h * HDc + col);
            Aw[ss][col] = f2tf(v.x*w); Aw[ss][col+1] = f2tf(v.y*w);
            Aw[ss][col+2] = f2tf(v.z*w); Aw[ss][col+3] = f2tf(v.w*w);
        }
        #pragma unroll
        for (int hh = 0; hh < 2; hh++) {
            int e = tid * 4 + hh * 1024; int col = e & 127; int ss = e >> 7;
            float4 v = *(const float4*)(base + (size_t)(s0 + ss) * CDc + DIc + col);
            Bsh[ss][col] = f2tf(v.x); Bsh[ss][col+1] = f2tf(v.y);
            Bsh[ss][col+2] = f2tf(v.z); Bsh[ss][col+3] = f2tf(v.w);
        }
        __syncthreads();
        mma_tile<2,4>(Aw, Bsh, acc, wm0, wn0, lane);
        __syncthreads();
    }
    float* out = g_st + (size_t)((d * NCc + c) * NHc + h) * HDc * DSc;
    int gid = lane >> 2, t4 = lane & 3;
    #pragma unroll
    for (int mi = 0; mi < 2; mi++) {
        int r0 = wm0 + mi * 16 + gid, r1 = r0 + 8;
        #pragma unroll
        for (int nj = 0; nj < 4; nj++) {
            int c0 = wn0 + nj * 8 + t4 * 2;
            out[r0 * DSc + c0]     = acc[mi][nj][0];
            out[r0 * DSc + c0 + 1] = acc[mi][nj][1];
            out[r1 * DSc + c0]     = acc[mi][nj][2];
            out[r1 * DSc + c0 + 1] = acc[mi][nj][3];
        }
    }
}

// ---------------- 6. inter-chunk scan ----------------
__global__ void __launch_bounds__(256) k_chunkscan() {
    int dh = blockIdx.x; int d = dh >> 3, h = dh & 7;
    int tid = threadIdx.x;
    float carry[32];
    #pragma unroll
    for (int t = 0; t < 32; t++) carry[t] = 0.f;
    for (int c = 0; c < NCc; c++) {
        float cd = __expf(g_dA[(size_t)(d * Lc + c * CSc + 255) * NHc + h]);
        size_t off = (size_t)((d * NCc + c) * NHc + h) * 8192;
        #pragma unroll
        for (int t = 0; t < 32; t++) {
            int e = tid + t * 256;
            g_pv[off + e] = carry[t];
            carry[t] = carry[t] * cd + g_st[off + e];
        }
    }
}

// ---------------- 7. merged SSD y: y = diag + exp(dAi)*(C@pv^T) + D*x ----------------
__global__ void __launch_bounds__(256) k_ssd_y(const float* __restrict__ D_param) {
    int i0 = blockIdx.x * 128;
    int z  = blockIdx.z; int d = z >> 7, c = (z >> 3) & 15, h = z & 7;
    __shared__ float Ss[16][LDT], Xs[16][LDT];
    __shared__ float daF[256], dtF[256], eI[128];
    int tid = threadIdx.x, wid = tid >> 5, lane = tid & 31;
    int wm0 = (wid & 3) * 32, wn0 = (wid >> 2) * 32;
    daF[tid] = g_dA[(size_t)(d * Lc + c * CSc + tid) * NHc + h];
    dtF[tid] = g_dt[(size_t)(d * Lc + c * CSc + tid) * NHc + h];
    __syncthreads();
    if (tid < 128) eI[tid] = __expf(daF[i0 + tid]);
    __syncthreads();
    const float* cbb   = g_CB + (size_t)(d * NCc + c) * CSc * CSc;
    const float* base  = g_xBC + (size_t)(d * Lc + c * CSc) * CDc;
    const float* xbase = base + h * HDc;
    float acc[2][4][4] = {};
    // ---- phase 1: diag (K = 256 over j) ----
    for (int j0 = 0; j0 < CSc; j0 += 16) {
        #pragma unroll
        for (int hh = 0; hh < 2; hh++) {    // score tile Ss[j][i]
            int e = tid * 4 + hh * 1024; int kk = e & 15; int ii = e >> 4;
            float4 v = *(const float4*)(cbb + (i0 + ii) * CSc + j0 + kk);
            float r[4] = {v.x, v.y, v.z, v.w};
            float dai = daF[i0 + ii];
            int ig = i0 + ii;
            #pragma unroll
            for (int q = 0; q < 4; q++) {
                int jg = j0 + kk + q;
                float sv = 0.f;
                if (jg <= ig) sv = r[q] * __expf(dai - daF[jg]) * dtF[jg];
                Ss[kk + q][ii] = f2tf(sv);
            }
        }
        {   // X tile Xs[j][p]
            int e = tid * 4; int p = e & 63; int jj = e >> 6;
            float4 v = *(const float4*)(xbase + (size_t)(j0 + jj) * CDc + p);
            Xs[jj][p] = f2tf(v.x); Xs[jj][p+1] = f2tf(v.y);
            Xs[jj][p+2] = f2tf(v.z); Xs[jj][p+3] = f2tf(v.w);
        }
        __syncthreads();
        mma_tile<2,4>(Ss, Xs, acc, wm0, wn0, lane);
        __syncthreads();
    }
    // ---- phase 2: off-diag, exp(dAi) folded into C rows (K = 128) ----
    const float* Cb = base + (size_t)i0 * CDc + (DIc + DSc);
    const float* pv = g_pv + (size_t)((d * NCc + c) * NHc + h) * HDc * DSc;
    for (int k0 = 0; k0 < DSc; k0 += 16) {
        #pragma unroll
        for (int hh = 0; hh < 2; hh++) {    // scaled C tile
            int e = tid * 4 + hh * 1024; int kk = e & 15; int ii = e >> 4;
            float4 v = *(const float4*)(Cb + (size_t)ii * CDc + k0 + kk);
            float ei = eI[ii];
            Ss[kk][ii]   = f2tf(v.x * ei); Ss[kk+1][ii] = f2tf(v.y * ei);
            Ss[kk+2][ii] = f2tf(v.z * ei); Ss[kk+3][ii] = f2tf(v.w * ei);
        }
        {   // pv tile
            int e = tid * 4; int kk = e & 15; int rr = e >> 4;
            float4 v = *(const float4*)(pv + (size_t)rr * DSc + k0 + kk);
            Xs[kk][rr] = f2tf(v.x); Xs[kk+1][rr] = f2tf(v.y);
            Xs[kk+2][rr] = f2tf(v.z); Xs[kk+3][rr] = f2tf(v.w);
        }
        __syncthreads();
        mma_tile<2,4>(Ss, Xs, acc, wm0, wn0, lane);
        __syncthreads();
    }
    float Dh = D_param[d * NHc + h];
    int gid = lane >> 2, t4 = lane & 3;
    #pragma unroll
    for (int mi = 0; mi < 2; mi++) {
        int lr0 = wm0 + mi * 16 + gid, lr1 = lr0 + 8;
        int l0 = c * CSc + i0 + lr0, l1 = c * CSc + i0 + lr1;
        #pragma unroll
        for (int nj = 0; nj < 4; nj++) {
            int p0 = wn0 + nj * 8 + t4 * 2;
            size_t y0 = (size_t)(d * Lc + l0) * DIc + h * HDc + p0;
            size_t y1 = (size_t)(d * Lc + l1) * DIc + h * HDc + p0;
            size_t x0 = (size_t)(d * Lc + l0) * CDc + h * HDc + p0;
            size_t x1 = (size_t)(d * Lc + l1) * CDc + h * HDc + p0;
            g_y[y0]     = acc[mi][nj][0] + Dh * g_xBC[x0];
            g_y[y0 + 1] = acc[mi][nj][1] + Dh * g_xBC[x0 + 1];
            g_y[y1]     = acc[mi][nj][2] + Dh * g_xBC[x1];
            g_y[y1 + 1] = acc[mi][nj][3] + Dh * g_xBC[x1 + 1];
        }
    }
}

// ---------------- 8. gate + RMSNorm ----------------
__global__ void __launch_bounds__(256) k_norm(const float* __restrict__ norm_w) {
    int l = blockIdx.x, d = blockIdx.y, tid = threadIdx.x;
    float v[2]; float ss = 0.f;
    #pragma unroll
    for (int t = 0; t < 2; t++) {
        int j = tid + t * 256;
        float zz = g_Z[(size_t)(d * Lc + l) * DIPc + j];
        float yy = g_y[(size_t)(d * Lc + l) * DIc + j];
        float val = yy * silu_f(zz);
        v[t] = val; ss += val * val;
    }
    __shared__ float red[256];
    red[tid] = ss; __syncthreads();
    for (int o = 128; o > 0; o >>= 1) { if (tid < o) red[tid] += red[tid + o]; __syncthreads(); }
    float scale = rsqrtf(red[0] / (float)DIc + EPSc);
    #pragma unroll
    for (int t = 0; t < 2; t++) {
        int j = tid + t * 256;
        g_y[(size_t)(d * Lc + l) * DIc + j] = v[t] * scale * norm_w[d * DIc + j];
    }
}

// ---------------- 9. out-proj (double-buffered) + permuted scatter ----------------
__global__ void __launch_bounds__(256) k_outproj(const float* __restrict__ Wout) {
    int d = blockIdx.z;
    int m0 = blockIdx.x * 128, n0 = blockIdx.y * 128;
    const float* A = g_y + (size_t)d * Lc * DIc + (size_t)m0 * DIc;
    const float* B = Wout + (size_t)d * DMc * DIc + (size_t)n0 * DIc;
    __shared__ float As[2][16][LDT], Bs[2][16][LDT];
    int tid = threadIdx.x, wid = tid >> 5, lane = tid & 31;
    int wm0 = (wid & 1) * 64, wn0 = (wid >> 1) * 32;
    float acc[4][4][4] = {};
    float4 ra[2], rb[2];
    fetch128(A, DIc, 0, ra, tid); fetch128(B, DIc, 0, rb, tid);
    store128(ra, As[0], tid); store128(rb, Bs[0], tid);
    __syncthreads();
    const int NT = DIc / 16;
    for (int t = 0; t < NT; t++) {
        int cur = t & 1;
        if (t + 1 < NT) {
            fetch128(A, DIc, (t + 1) * 16, ra, tid);
            fetch128(B, DIc, (t + 1) * 16, rb, tid);
        }
        mma_tile<4,4>(As[cur], Bs[cur], acc, wm0, wn0, lane);
        if (t + 1 < NT) { store128(ra, As[cur ^ 1], tid); store128(rb, Bs[cur ^ 1], tid); }
        __syncthreads();
    }
    int gid = lane >> 2, t4 = lane & 3;
    #pragma unroll
    for (int mi = 0; mi < 4; mi++) {
        #pragma unroll
        for (int half = 0; half < 2; half++) {
            int l = m0 + wm0 + mi * 16 + gid + half * 8;
            int r;
            if      (d == 0) r = l;
            else if (d == 1) r = 4095 - l;
            else if (d == 2) r = (l & 63) * 64 + (l >> 6);
            else             { int lv = 4095 - l; r = (lv & 63) * 64 + (lv >> 6); }
            #pragma unroll
            for (int nj = 0; nj < 4; nj++) {
                int c0 = n0 + wn0 + nj * 8 + t4 * 2;
                g_cat[(size_t)r * (4 * DMc) + d * DMc + c0]     = acc[mi][nj][half * 2];
                g_cat[(size_t)r * (4 * DMc) + d * DMc + c0 + 1] = acc[mi][nj][half * 2 + 1];
            }
        }
    }
}

// ---------------- 10. final GEMM (double-buffered, SiLU fused on A) ----------------
__global__ void __launch_bounds__(256) k_final(const float* __restrict__ Wf,
                                               float* __restrict__ out) {
    int m0 = blockIdx.x * 128, n0 = blockIdx.y * 64;
    const float* A = g_cat + (size_t)m0 * 1024;
    const float* B = Wf + (size_t)n0 * 1024;
    __shared__ float As[2][16][LDT], Bs[2][16][LDT];
    int tid = threadIdx.x, wid = tid >> 5, lane = tid & 31;
    int wm0 = (wid & 3) * 32, wn0 = (wid >> 2) * 32;
    float acc[2][4][4] = {};
    float4 ra[2], rb;
    fetch128(A, 1024, 0, ra, tid); fetch64(B, 1024, 0, rb, tid);
    store128s(ra, As[0], tid); store64(rb, Bs[0], tid);
    __syncthreads();
    const int NT = 1024 / 16;
    for (int t = 0; t < NT; t++) {
        int cur = t & 1;
        if (t + 1 < NT) {
            fetch128(A, 1024, (t + 1) * 16, ra, tid);
            fetch64 (B, 1024, (t + 1) * 16, rb, tid);
        }
        mma_tile<2,4>(As[cur], Bs[cur], acc, wm0, wn0, lane);
        if (t + 1 < NT) { store128s(ra, As[cur ^ 1], tid); store64(rb, Bs[cur ^ 1], tid); }
        __syncthreads();
    }
    int gid = lane >> 2, t4 = lane & 3;
    #pragma unroll
    for (int mi = 0; mi < 2; mi++) {
        int r0 = m0 + wm0 + mi * 16 + gid, r1 = r0 + 8;
        #pragma unroll
        for (int nj = 0; nj < 4; nj++) {
            int c0 = n0 + wn0 + nj * 8 + t4 * 2;
            out[(size_t)r0 * DMc + c0]     = acc[mi][nj][0];
            out[(size_t)r0 * DMc + c0 + 1] = acc[mi][nj][1];
            out[(size_t)r1 * DMc + c0]     = acc[mi][nj][2];
            out[(size_t)r1 * DMc + c0 + 1] = acc[mi][nj][3];
        }
    }
}

// ---------------- launcher ----------------
extern "C" void kernel_launch(void* const* d_in, const int* in_sizes, int n_in,
                              void* d_out, int out_size) {
    const float* pts      = (const float*)d_in[0];
    const float* in_proj  = (const float*)d_in[2];
    const float* conv_w   = (const float*)d_in[3];
    const float* conv_b   = (const float*)d_in[4];
    const float* dt_bias  = (const float*)d_in[5];
    const float* A_log    = (const float*)d_in[6];
    const float* D_param  = (const float*)d_in[7];
    const float* norm_w   = (const float*)d_in[8];
    const float* outp_w   = (const float*)d_in[9];
    const float* final_w  = (const float*)d_in[10];
    float* out = (float*)d_out;

    k_buildU   <<<dim3(128, 8, 4), dim3(32, 8)>>>(pts);
    k_inproj   <<<dim3(32, 11, 4), 256>>>(in_proj);
    k_conv     <<<dim3(4096, 4),   256>>>(conv_w, conv_b, dt_bias);
    k_scan     <<<dim3(16, 8, 4),  256>>>(A_log);
    k_cb       <<<dim3(2, 2, 64),  256>>>();
    k_states   <<<dim3(1, 1, 512), 256>>>();
    k_chunkscan<<<32, 256>>>();
    k_ssd_y    <<<dim3(2, 1, 512), 256>>>(D_param);
    k_norm     <<<dim3(4096, 4),   256>>>(norm_w);
    k_outproj  <<<dim3(32, 2, 4),  256>>>(outp_w);
    k_final    <<<dim3(32, 4),     256>>>(final_w, out);
}